// round 12
// baseline (speedup 1.0000x reference)
#include <cuda_runtime.h>
#include <math.h>
#include <stdint.h>

#define NA 20000
#define NE 640000
#define DD 128
#define GG 32
#define HH 8
#define NIT 4
#define NSM 148

// ---------------- device scratch ----------------
__device__ float    g_Wfil[(size_t)NE * DD];
__device__ int      g_ssrc[NE];     // src, sorted by dst
__device__ int      g_sdst[NE];
__device__ int      g_lsrc[NE];     // live subset, sorted by dst
__device__ int      g_lpos[NE];
__device__ int      g_ldst[NE];
__device__ int      g_cnt_all[NA];  // statically zero; re-zeroed by final k_out
__device__ int      g_cnt_live[NA];
__device__ int      g_off_all[NA];
__device__ int      g_off_live[NA];
__device__ int      g_nlive;
__device__ float    g_h[NA * DD];
__device__ float    g_Q[NA * DD];
__device__ float    g_K[NA * DD];
__device__ float    g_s[NE * HH];
__device__ float    g_U[(size_t)NA * 1024];   // per-atom [8 heads][128 dims] aggregate
__device__ float    g_msg[NA * DD];

__device__ __forceinline__ float edge_r(const float* xyz, int s, int d) {
    float dx = xyz[3 * s]     - xyz[3 * d];
    float dy = xyz[3 * s + 1] - xyz[3 * d + 1];
    float dz = xyz[3 * s + 2] - xyz[3 * d + 2];
    return sqrtf(dx * dx + dy * dy + dz * dz + 1e-12f);
}

// ---------------- tf32 MMA core with fragment-major smem ----------------
__device__ __forceinline__ uint32_t f2tf(float f) {
    uint32_t u;
    asm("cvt.rna.tf32.f32 %0, %1;" : "=r"(u) : "f"(f));
    return u;
}
__device__ __forceinline__ float f2tff(float f) { return __uint_as_float(f2tf(f)); }

__device__ __forceinline__ void mma8(float4& d,
                                     uint32_t a0, uint32_t a1, uint32_t a2, uint32_t a3,
                                     uint32_t b0, uint32_t b1) {
    asm volatile(
        "mma.sync.aligned.m16n8k8.row.col.f32.tf32.tf32.f32 "
        "{%0,%1,%2,%3},{%4,%5,%6,%7},{%8,%9},{%0,%1,%2,%3};"
        : "+f"(d.x), "+f"(d.y), "+f"(d.z), "+f"(d.w)
        : "r"(a0), "r"(a1), "r"(a2), "r"(a3), "r"(b0), "r"(b1));
}
template <int KB>
__device__ __forceinline__ int fragA_idx(int r, int k) {
    return (((r >> 4) * KB + (k >> 3)) << 7) + (((r & 7) * 4 + (k & 3)) << 2)
         + ((r >> 3) & 1) + (((k >> 2) & 1) << 1);
}
template <int KB>
__device__ __forceinline__ int fragB_idx(int k, int n) {
    return (((n >> 4) * KB + (k >> 3)) << 7) + (((n & 7) * 4 + (k & 3)) << 2)
         + (((n >> 3) & 1) << 1) + ((k >> 2) & 1);
}
#define FAU(x) __float_as_uint(x)
template <int KB>
__device__ __forceinline__ void mma_tile_frag(const float* __restrict__ sA,
                                              const float* __restrict__ sB,
                                              int wm, int wn, int lane,
                                              float4 acc[2][4]) {
    const float4* A = (const float4*)sA;
    const float4* B = (const float4*)sB;
#pragma unroll
    for (int kk = 0; kk < KB; kk++) {
        float4 a0 = A[((2 * wm)     * KB + kk) * 32 + lane];
        float4 a1 = A[((2 * wm + 1) * KB + kk) * 32 + lane];
        float4 b0 = B[((2 * wn)     * KB + kk) * 32 + lane];
        float4 b1 = B[((2 * wn + 1) * KB + kk) * 32 + lane];
        mma8(acc[0][0], FAU(a0.x), FAU(a0.y), FAU(a0.z), FAU(a0.w), FAU(b0.x), FAU(b0.y));
        mma8(acc[1][0], FAU(a1.x), FAU(a1.y), FAU(a1.z), FAU(a1.w), FAU(b0.x), FAU(b0.y));
        mma8(acc[0][1], FAU(a0.x), FAU(a0.y), FAU(a0.z), FAU(a0.w), FAU(b0.z), FAU(b0.w));
        mma8(acc[1][1], FAU(a1.x), FAU(a1.y), FAU(a1.z), FAU(a1.w), FAU(b0.z), FAU(b0.w));
        mma8(acc[0][2], FAU(a0.x), FAU(a0.y), FAU(a0.z), FAU(a0.w), FAU(b1.x), FAU(b1.y));
        mma8(acc[1][2], FAU(a1.x), FAU(a1.y), FAU(a1.z), FAU(a1.w), FAU(b1.x), FAU(b1.y));
        mma8(acc[0][3], FAU(a0.x), FAU(a0.y), FAU(a0.z), FAU(a0.w), FAU(b1.z), FAU(b1.w));
        mma8(acc[1][3], FAU(a1.x), FAU(a1.y), FAU(a1.z), FAU(a1.w), FAU(b1.z), FAU(b1.w));
    }
}
__device__ __forceinline__ void zacc4(float4 acc[2][4]) {
#pragma unroll
    for (int i = 0; i < 2; i++)
#pragma unroll
        for (int j = 0; j < 4; j++) acc[i][j] = make_float4(0.f, 0.f, 0.f, 0.f);
}

// ---------------- setup ----------------
__global__ void k_hist(const float* __restrict__ xyz, const int* __restrict__ src,
                       const int* __restrict__ dst) {
    int e = blockIdx.x * blockDim.x + threadIdx.x;
    if (e >= NE) return;
    int s = src[e], d = dst[e];
    atomicAdd(&g_cnt_all[d], 1);
    if (edge_r(xyz, s, d) < 8.f) atomicAdd(&g_cnt_live[d], 1);
}

__global__ __launch_bounds__(512) void k_scan() {
    __shared__ int part[512];
    __shared__ int total;
    int t = threadIdx.x;
    const int CH = (NA + 511) / 512;
#pragma unroll 1
    for (int pass = 0; pass < 2; pass++) {
        int* cnt = pass ? g_cnt_live : g_cnt_all;
        int* off = pass ? g_off_live : g_off_all;
        int lo = t * CH, hi = min(lo + CH, NA);
        int s = 0;
        for (int i = lo; i < hi; i++) s += cnt[i];
        part[t] = s;
        __syncthreads();
        if (t == 0) {
            int run = 0;
            for (int i = 0; i < 512; i++) { int v = part[i]; part[i] = run; run += v; }
            total = run;
        }
        __syncthreads();
        int run = part[t];
        for (int i = lo; i < hi; i++) { int v = cnt[i]; off[i] = run; run += v; cnt[i] = 0; }
        if (pass == 1 && t == 0) g_nlive = total;
        __syncthreads();
    }
}

__global__ void k_scatter(const float* __restrict__ xyz, const int* __restrict__ src,
                          const int* __restrict__ dst) {
    int e = blockIdx.x * blockDim.x + threadIdx.x;
    if (e >= NE) return;
    int s = src[e], d = dst[e];
    int pos = g_off_all[d] + atomicAdd(&g_cnt_all[d], 1);
    g_ssrc[pos] = s;
    g_sdst[pos] = d;
    if (edge_r(xyz, s, d) < 8.f) {
        int lp = g_off_live[d] + atomicAdd(&g_cnt_live[d], 1);
        g_lsrc[lp] = s; g_ldst[lp] = d; g_lpos[lp] = pos;
    }
}

__global__ void k_embed(const float* __restrict__ emb, const int* __restrict__ z,
                        float* __restrict__ x) {
    int i = blockIdx.x * blockDim.x + threadIdx.x;
    if (i < NA * DD) {
        int n = i >> 7, d = i & 127;
        x[i] = emb[z[n] * DD + d];
    }
}

// ---------------- filter (persistent, tf32, fragment smem) ----------------
__global__ __launch_bounds__(512) void k_filter(
    const float* __restrict__ xyz,
    const float* __restrict__ Wl, const float* __restrict__ bl,
    const float* __restrict__ W1f, const float* __restrict__ b1f,
    const float* __restrict__ W2f, const float* __restrict__ b2f) {
    extern __shared__ float sm[];
    float* sf   = sm;
    float* sg   = sf + 4096;
    float* sW1t = sg + 16384;
    float* sWlt = sW1t + 4096;
    float* sW2t = sWlt + 4096;
    float* sr   = sW2t + 16384;
    float* sC   = sr + 128;
    float* sb1  = sC + 128;
    float* sb   = sb1 + 128;

    int tid = threadIdx.x, lane = tid & 31, w = tid >> 5;
    int wm = w & 3, wn = w >> 2;
    int g = lane >> 2, t4 = lane & 3;

    for (int i = tid; i < 32 * 128; i += 512) {
        int k = i >> 7, n = i & 127;
        sW1t[fragB_idx<4>(k, n)] = f2tff(W1f[i]);
        sWlt[fragB_idx<4>(k, n)] = f2tff(Wl[i]);
    }
    for (int i = tid; i < 128 * 128; i += 512) {
        int k = i >> 7, n = i & 127;
        sW2t[fragB_idx<16>(k, n)] = f2tff(W2f[i]);
    }
    if (tid < 128) { sb1[tid] = b1f[tid]; sb[tid] = bl[tid] + b2f[tid]; }

    int nlive = g_nlive;
    for (int tt = blockIdx.x; tt * 128 < nlive; tt += gridDim.x) {
        if (tid < 128) {
            int li = tt * 128 + tid;
            float r = 100.f, C = 0.f;
            if (li < nlive) {
                r = edge_r(xyz, g_lsrc[li], g_ldst[li]);
                C = (r < 8.f) ? (0.5f * (cospif(r * 0.125f) + 1.f)) : 0.f;
            }
            sr[tid] = r; sC[tid] = C;
        }
        __syncthreads();
        {
            int el = tid >> 2, kb = (tid & 3) * 8;
            float r = sr[el];
#pragma unroll
            for (int q = 0; q < 8; q++) {
                int k = kb + q;
                float off = (float)k * (8.f / 31.f);
                float u = (r - off) * (31.f / 8.f);
                sf[fragA_idx<4>(el, k)] = f2tff(__expf(-0.5f * u * u));
            }
        }
        __syncthreads();

        float4 acc[2][4];
        zacc4(acc);
        mma_tile_frag<4>(sf, sW1t, wm, wn, lane, acc);
        __syncthreads();
#pragma unroll
        for (int mi = 0; mi < 2; mi++) {
            int r = 32 * wm + 16 * mi + g;
#pragma unroll
            for (int jl = 0; jl < 4; jl++) {
                int c = 32 * wn + 8 * jl + 2 * t4;
                float4 d = acc[mi][jl];
                float v0 = d.x + sb1[c], v1 = d.y + sb1[c + 1];
                float v2 = d.z + sb1[c], v3 = d.w + sb1[c + 1];
                sg[fragA_idx<16>(r, c)]         = f2tff(v0 / (1.f + __expf(-v0)));
                sg[fragA_idx<16>(r, c + 1)]     = f2tff(v1 / (1.f + __expf(-v1)));
                sg[fragA_idx<16>(r + 8, c)]     = f2tff(v2 / (1.f + __expf(-v2)));
                sg[fragA_idx<16>(r + 8, c + 1)] = f2tff(v3 / (1.f + __expf(-v3)));
            }
        }
        __syncthreads();

        zacc4(acc);
        mma_tile_frag<4>(sf, sWlt, wm, wn, lane, acc);
        mma_tile_frag<16>(sg, sW2t, wm, wn, lane, acc);

#pragma unroll
        for (int mi = 0; mi < 2; mi++) {
            int r = 32 * wm + 16 * mi + g;
#pragma unroll
            for (int jl = 0; jl < 4; jl++) {
                int c = 32 * wn + 8 * jl + 2 * t4;
                float4 d = acc[mi][jl];
                int li0 = tt * 128 + r, li1 = li0 + 8;
                if (li0 < nlive) {
                    float Cv = sC[r];
                    *(float2*)(g_Wfil + (size_t)li0 * 128 + c) =
                        make_float2((d.x + sb[c]) * Cv, (d.y + sb[c + 1]) * Cv);
                }
                if (li1 < nlive) {
                    float Cv = sC[r + 8];
                    *(float2*)(g_Wfil + (size_t)li1 * 128 + c) =
                        make_float2((d.z + sb[c]) * Cv, (d.w + sb[c + 1]) * Cv);
                }
            }
        }
        __syncthreads();
    }
}

// ---------------- fused out+hqk: x += msg@Wo; h = x+te; Q = h@Wq; K = h@Wk ----------------
__global__ __launch_bounds__(512) void k_oqk(float* __restrict__ x,
                                             const float* __restrict__ te,
                                             const float* __restrict__ Wo,
                                             const float* __restrict__ Wq,
                                             const float* __restrict__ Wk, int it) {
    extern __shared__ float sm[];
    float* sA = sm;
    float* sB = sm + 16384;
    int tid = threadIdx.x, lane = tid & 31, w = tid >> 5;
    int wm = w & 3, wn = w >> 2;
    int g = lane >> 2, t4 = lane & 3;
    int n0 = blockIdx.x * 128;

    float4 acc[2][4];
    zacc4(acc);
    if (it > 0) {
        for (int i = tid; i < 128 * 128; i += 512) {
            int r = i >> 7, c = i & 127, n = n0 + r;
            sA[fragA_idx<16>(r, c)] = (n < NA) ? f2tff(g_msg[(size_t)n * 128 + c]) : 0.f;
        }
        for (int i = tid; i < 128 * 128; i += 512) {
            int k = i >> 7, n = i & 127;
            sB[fragB_idx<16>(k, n)] = f2tff(Wo[i]);
        }
        __syncthreads();
        mma_tile_frag<16>(sA, sB, wm, wn, lane, acc);
        __syncthreads();
    }
#pragma unroll
    for (int mi = 0; mi < 2; mi++) {
        int r = 32 * wm + 16 * mi + g;
#pragma unroll
        for (int jl = 0; jl < 4; jl++) {
            int c = 32 * wn + 8 * jl + 2 * t4;
            float4 d = acc[mi][jl];
            float te0 = te[it * 128 + c], te1 = te[it * 128 + c + 1];
            int n1 = n0 + r, n2 = n1 + 8;
            float h00 = 0.f, h01 = 0.f, h10 = 0.f, h11 = 0.f;
            if (n1 < NA) {
                float2 xv = *(float2*)(x + (size_t)n1 * 128 + c);
                xv.x += d.x; xv.y += d.y;
                *(float2*)(x + (size_t)n1 * 128 + c) = xv;
                h00 = xv.x + te0; h01 = xv.y + te1;
                *(float2*)(g_h + (size_t)n1 * 128 + c) = make_float2(h00, h01);
            }
            if (n2 < NA) {
                float2 xv = *(float2*)(x + (size_t)n2 * 128 + c);
                xv.x += d.z; xv.y += d.w;
                *(float2*)(x + (size_t)n2 * 128 + c) = xv;
                h10 = xv.x + te0; h11 = xv.y + te1;
                *(float2*)(g_h + (size_t)n2 * 128 + c) = make_float2(h10, h11);
            }
            sA[fragA_idx<16>(r, c)]         = f2tff(h00);
            sA[fragA_idx<16>(r, c + 1)]     = f2tff(h01);
            sA[fragA_idx<16>(r + 8, c)]     = f2tff(h10);
            sA[fragA_idx<16>(r + 8, c + 1)] = f2tff(h11);
        }
    }
    for (int i = tid; i < 128 * 128; i += 512) {
        int k = i >> 7, n = i & 127;
        sB[fragB_idx<16>(k, n)] = f2tff(Wq[i]);
    }
    __syncthreads();
    zacc4(acc);
    mma_tile_frag<16>(sA, sB, wm, wn, lane, acc);
#pragma unroll
    for (int mi = 0; mi < 2; mi++) {
        int r = 32 * wm + 16 * mi + g;
#pragma unroll
        for (int jl = 0; jl < 4; jl++) {
            int c = 32 * wn + 8 * jl + 2 * t4;
            float4 d = acc[mi][jl];
            int n1 = n0 + r, n2 = n1 + 8;
            if (n1 < NA) *(float2*)(g_Q + (size_t)n1 * 128 + c) = make_float2(d.x, d.y);
            if (n2 < NA) *(float2*)(g_Q + (size_t)n2 * 128 + c) = make_float2(d.z, d.w);
        }
    }
    __syncthreads();
    for (int i = tid; i < 128 * 128; i += 512) {
        int k = i >> 7, n = i & 127;
        sB[fragB_idx<16>(k, n)] = f2tff(Wk[i]);
    }
    __syncthreads();
    zacc4(acc);
    mma_tile_frag<16>(sA, sB, wm, wn, lane, acc);
#pragma unroll
    for (int mi = 0; mi < 2; mi++) {
        int r = 32 * wm + 16 * mi + g;
#pragma unroll
        for (int jl = 0; jl < 4; jl++) {
            int c = 32 * wn + 8 * jl + 2 * t4;
            float4 d = acc[mi][jl];
            int n1 = n0 + r, n2 = n1 + 8;
            if (n1 < NA) *(float2*)(g_K + (size_t)n1 * 128 + c) = make_float2(d.x, d.y);
            if (n2 < NA) *(float2*)(g_K + (size_t)n2 * 128 + c) = make_float2(d.z, d.w);
        }
    }
}

// ---------------- scores: one warp per 4 edges, lane = eo*8 + h ----------------
__global__ __launch_bounds__(256) void k_score() {
    int w = (blockIdx.x * blockDim.x + threadIdx.x) >> 5;
    int lane = threadIdx.x & 31;
    int h = lane & 7, eo = lane >> 3;
    int e = w * 4 + eo;
    if (e >= NE) return;
    int s = g_ssrc[e], d = g_sdst[e];
    const float4* qp = (const float4*)(g_Q + (size_t)d * 128 + h * 16);
    const float4* kp = (const float4*)(g_K + (size_t)s * 128 + h * 16);
    float4 q0 = qp[0], q1 = qp[1], q2 = qp[2], q3 = qp[3];
    float4 k0 = kp[0], k1 = kp[1], k2 = kp[2], k3 = kp[3];
    float p = q0.x * k0.x + q0.y * k0.y + q0.z * k0.z + q0.w * k0.w
            + q1.x * k1.x + q1.y * k1.y + q1.z * k1.z + q1.w * k1.w
            + q2.x * k2.x + q2.y * k2.y + q2.z * k2.z + q2.w * k2.w
            + q3.x * k3.x + q3.y * k3.y + q3.z * k3.z + q3.w * k3.w;
    g_s[(size_t)e * 8 + h] = p * 0.25f;
}

// ---------------- per-atom normalize + U aggregation; one warp per atom ----------------
__global__ __launch_bounds__(256) void k_attn2() {
    int warp = (blockIdx.x * blockDim.x + threadIdx.x) >> 5;
    int lane = threadIdx.x & 31;
    if (warp >= NA) return;
    int d = warp;
    int beg = g_off_all[d], cnt = g_cnt_all[d];
    int h = lane & 7, eo = lane >> 3;

    float acc[8][4];
#pragma unroll
    for (int b = 0; b < 8; b++)
#pragma unroll
        for (int j = 0; j < 4; j++) acc[b][j] = 0.f;

    if (cnt > 0) {
        // online max/denominator over this lane's edge slice (stride 4)
        float m = -1e30f, den = 0.f;
        for (int base = 0; base < cnt; base += 4) {
            int i = base + eo;
            if (i < cnt) {
                float p = g_s[(size_t)(beg + i) * 8 + h];
                float mn = fmaxf(m, p);
                den = den * __expf(m - mn) + __expf(p - mn);
                m = mn;
            }
        }
        // merge across eo slices (lanes differing in bits 3,4)
#pragma unroll
        for (int delta = 8; delta <= 16; delta <<= 1) {
            float om = __shfl_xor_sync(0xffffffffu, m, delta);
            float od = __shfl_xor_sync(0xffffffffu, den, delta);
            float mn = fmaxf(m, om);
            den = den * __expf(m - mn) + od * __expf(om - mn);
            m = mn;
        }
        float inv = 1.f / (den + 1e-12f);
        for (int base = 0; base < cnt; base += 4) {
            int i = base + eo;
            if (i < cnt) {
                size_t o = (size_t)(beg + i) * 8 + h;
                g_s[o] = __expf(g_s[o] - m) * inv;
            }
        }
        __syncwarp();
        // U aggregation over live edges
        int lbeg = g_off_live[d], lcnt = g_cnt_live[d];
        for (int i = 0; i < lcnt; i++) {
            int lp = lbeg + i;
            int e = g_lpos[lp];
            int s = g_lsrc[lp];
            float4 a0 = *(const float4*)(g_s + (size_t)e * 8);
            float4 a1 = *(const float4*)(g_s + (size_t)e * 8 + 4);
            float4 hv = *(const float4*)(g_h + (size_t)s * 128 + lane * 4);
            float4 wv = *(const float4*)(g_Wfil + (size_t)lp * 128 + lane * 4);
            float u0 = hv.x * wv.x, u1 = hv.y * wv.y;
            float u2 = hv.z * wv.z, u3 = hv.w * wv.w;
            float ab[8] = {a0.x, a0.y, a0.z, a0.w, a1.x, a1.y, a1.z, a1.w};
#pragma unroll
            for (int b = 0; b < 8; b++) {
                acc[b][0] += ab[b] * u0; acc[b][1] += ab[b] * u1;
                acc[b][2] += ab[b] * u2; acc[b][3] += ab[b] * u3;
            }
        }
    }
    float* up = g_U + (size_t)d * 1024 + lane * 4;
#pragma unroll
    for (int b = 0; b < 8; b++)
        *(float4*)(up + b * 128) = make_float4(acc[b][0], acc[b][1], acc[b][2], acc[b][3]);
}

// ---------------- ugemm: msg[:, 16b:16b+16] = U[:, b, :] @ Wv[:, 16b:16b+16] ----------------
__global__ __launch_bounds__(256) void k_ugemm(const float* __restrict__ Wv) {
    extern __shared__ float sm[];
    float* sU = sm;            // 128 atoms x 128 dims (64 KB)
    float* sW = sm + 16384;    // 128 x 16 (8 KB)
    int b = blockIdx.y, n0 = blockIdx.x * 128, tid = threadIdx.x;

    for (int i = tid; i < 128 * 16; i += 256) {
        int k = i >> 4, c = i & 15;
        sW[i] = Wv[k * 128 + b * 16 + c];
    }
    for (int i = tid; i < 128 * 32; i += 256) {
        int r = i >> 5, kq = i & 31;
        int n = n0 + r;
        float4 v = (n < NA) ? *(const float4*)(g_U + (size_t)n * 1024 + b * 128 + kq * 4)
                            : make_float4(0.f, 0.f, 0.f, 0.f);
        *(float4*)(sU + r * 128 + kq * 4) = v;
    }
    __syncthreads();

    int col = tid & 15, rg = tid >> 4;   // rows rg*8..rg*8+7
    float acc[8] = {0.f, 0.f, 0.f, 0.f, 0.f, 0.f, 0.f, 0.f};
#pragma unroll 4
    for (int k4 = 0; k4 < 128; k4 += 4) {
        float bw[4];
#pragma unroll
        for (int q = 0; q < 4; q++) bw[q] = sW[(k4 + q) * 16 + col];
#pragma unroll
        for (int j = 0; j < 8; j++) {
            float4 av = *(const float4*)(sU + (rg * 8 + j) * 128 + k4);
            acc[j] += av.x * bw[0] + av.y * bw[1] + av.z * bw[2] + av.w * bw[3];
        }
    }
#pragma unroll
    for (int j = 0; j < 8; j++) {
        int n = n0 + rg * 8 + j;
        if (n < NA) g_msg[(size_t)n * 128 + b * 16 + col] = acc[j];
    }
}

// ---------------- final: x += msg @ Wo; reset counters for next call ----------------
__global__ __launch_bounds__(512) void k_out(float* __restrict__ x,
                                             const float* __restrict__ Wo) {
    extern __shared__ float sm[];
    float* sA  = sm;
    float* sBt = sA + 16384;
    int tid = threadIdx.x, lane = tid & 31, w = tid >> 5;
    int wm = w & 3, wn = w >> 2;
    int g = lane >> 2, t4 = lane & 3;
    int n0 = blockIdx.x * 128;

    int gidx = blockIdx.x * 512 + tid;
    if (gidx < NA) { g_cnt_all[gidx] = 0; g_cnt_live[gidx] = 0; }

    for (int i = tid; i < 128 * 128; i += 512) {
        int r = i >> 7, c = i & 127;
        int n = n0 + r;
        sA[fragA_idx<16>(r, c)] = (n < NA) ? f2tff(g_msg[(size_t)n * 128 + c]) : 0.f;
    }
    for (int i = tid; i < 128 * 128; i += 512) {
        int k = i >> 7, n = i & 127;
        sBt[fragB_idx<16>(k, n)] = f2tff(Wo[i]);
    }
    __syncthreads();

    float4 acc[2][4];
    zacc4(acc);
    mma_tile_frag<16>(sA, sBt, wm, wn, lane, acc);
#pragma unroll
    for (int mi = 0; mi < 2; mi++) {
        int r = 32 * wm + 16 * mi + g;
#pragma unroll
        for (int jl = 0; jl < 4; jl++) {
            int c = 32 * wn + 8 * jl + 2 * t4;
            float4 d = acc[mi][jl];
            int n1 = n0 + r, n2 = n1 + 8;
            if (n1 < NA) {
                float2 o = *(float2*)(x + (size_t)n1 * 128 + c);
                o.x += d.x; o.y += d.y;
                *(float2*)(x + (size_t)n1 * 128 + c) = o;
            }
            if (n2 < NA) {
                float2 o = *(float2*)(x + (size_t)n2 * 128 + c);
                o.x += d.z; o.y += d.w;
                *(float2*)(x + (size_t)n2 * 128 + c) = o;
            }
        }
    }
}

// ---------------- launch ----------------
extern "C" void kernel_launch(void* const* d_in, const int* in_sizes, int n_in,
                              void* d_out, int out_size) {
    const float* xyz = (const float*)d_in[0];
    const float* emb = (const float*)d_in[1];
    const float* te  = (const float*)d_in[2];
    const float* Wl  = (const float*)d_in[3];
    const float* bl  = (const float*)d_in[4];
    const float* W1f = (const float*)d_in[5];
    const float* b1f = (const float*)d_in[6];
    const float* W2f = (const float*)d_in[7];
    const float* b2f = (const float*)d_in[8];
    const float* Wq  = (const float*)d_in[9];
    const float* Wk  = (const float*)d_in[10];
    const float* Wv  = (const float*)d_in[11];
    const float* Wo  = (const float*)d_in[12];
    const int*   z   = (const int*)d_in[13];
    const int*   src = (const int*)d_in[14];
    const int*   dst = (const int*)d_in[15];
    float* x = (float*)d_out;

    const int SM_FILTER = (4096 + 16384 + 4096 + 4096 + 16384 + 4 * 128) * 4;
    const int SM_OQK    = (2 * 16384) * 4;
    const int SM_UGEMM  = (16384 + 128 * 16) * 4;   // 73728
    const int SM_OUT    = (2 * 16384) * 4;

    cudaFuncSetAttribute(k_filter, cudaFuncAttributeMaxDynamicSharedMemorySize, SM_FILTER);
    cudaFuncSetAttribute(k_oqk,    cudaFuncAttributeMaxDynamicSharedMemorySize, SM_OQK);
    cudaFuncSetAttribute(k_ugemm,  cudaFuncAttributeMaxDynamicSharedMemorySize, SM_UGEMM);
    cudaFuncSetAttribute(k_out,    cudaFuncAttributeMaxDynamicSharedMemorySize, SM_OUT);

    k_hist<<<NE / 256, 256>>>(xyz, src, dst);
    k_scan<<<1, 512>>>();
    k_scatter<<<NE / 256, 256>>>(xyz, src, dst);
    k_filter<<<NSM, 512, SM_FILTER>>>(xyz, Wl, bl, W1f, b1f, W2f, b2f);
    k_embed<<<(NA * DD + 255) / 256, 256>>>(emb, z, x);

    const int NBLK = (NA + 127) / 128;   // 157
    dim3 ug(NBLK, 8);
    for (int it = 0; it < NIT; it++) {
        k_oqk<<<NBLK, 512, SM_OQK>>>(x, te, Wo, Wq, Wk, it);
        k_score<<<NE / 32, 256>>>();
        k_attn2<<<(NA * 32 + 255) / 256, 256>>>();
        k_ugemm<<<ug, 256, SM_UGEMM>>>(Wv);
    }
    k_out<<<NBLK, 512, SM_OUT>>>(x, Wo);
}

// round 13
// speedup vs baseline: 1.4000x; 1.4000x over previous
#include <cuda_runtime.h>
#include <math.h>
#include <stdint.h>

#define NA 20000
#define NE 640000
#define DD 128
#define GG 32
#define HH 8
#define NIT 4
#define NSM 148
#define NTAB 4096

// ---------------- device scratch ----------------
__device__ float    g_tab[(NTAB + 1) * DD];   // Wfil lookup table over r in [0,8]
__device__ int      g_ssrc[NE];     // src, sorted by dst
__device__ int      g_sdst[NE];
__device__ int      g_lsrc[NE];     // live subset, sorted by dst
__device__ int      g_lpos[NE];
__device__ float    g_lr[NE];       // live edge distance
__device__ int      g_cnt_all[NA];  // statically zero; re-zeroed by final k_out
__device__ int      g_cnt_live[NA];
__device__ int      g_off_all[NA];
__device__ int      g_off_live[NA];
__device__ int      g_nlive;
__device__ float    g_h[NA * DD];
__device__ float    g_Q[NA * DD];
__device__ float    g_K[NA * DD];
__device__ float    g_s[NE * HH];
__device__ float    g_U[(size_t)NA * 1024];   // per-atom [8 heads][128 dims] aggregate
__device__ float    g_msg[NA * DD];

__device__ __forceinline__ float edge_r(const float* xyz, int s, int d) {
    float dx = xyz[3 * s]     - xyz[3 * d];
    float dy = xyz[3 * s + 1] - xyz[3 * d + 1];
    float dz = xyz[3 * s + 2] - xyz[3 * d + 2];
    return sqrtf(dx * dx + dy * dy + dz * dz + 1e-12f);
}

// ---------------- tf32 MMA core with fragment-major smem ----------------
__device__ __forceinline__ uint32_t f2tf(float f) {
    uint32_t u;
    asm("cvt.rna.tf32.f32 %0, %1;" : "=r"(u) : "f"(f));
    return u;
}
__device__ __forceinline__ float f2tff(float f) { return __uint_as_float(f2tf(f)); }

__device__ __forceinline__ void mma8(float4& d,
                                     uint32_t a0, uint32_t a1, uint32_t a2, uint32_t a3,
                                     uint32_t b0, uint32_t b1) {
    asm volatile(
        "mma.sync.aligned.m16n8k8.row.col.f32.tf32.tf32.f32 "
        "{%0,%1,%2,%3},{%4,%5,%6,%7},{%8,%9},{%0,%1,%2,%3};"
        : "+f"(d.x), "+f"(d.y), "+f"(d.z), "+f"(d.w)
        : "r"(a0), "r"(a1), "r"(a2), "r"(a3), "r"(b0), "r"(b1));
}
template <int KB>
__device__ __forceinline__ int fragA_idx(int r, int k) {
    return (((r >> 4) * KB + (k >> 3)) << 7) + (((r & 7) * 4 + (k & 3)) << 2)
         + ((r >> 3) & 1) + (((k >> 2) & 1) << 1);
}
template <int KB>
__device__ __forceinline__ int fragB_idx(int k, int n) {
    return (((n >> 4) * KB + (k >> 3)) << 7) + (((n & 7) * 4 + (k & 3)) << 2)
         + (((n >> 3) & 1) << 1) + ((k >> 2) & 1);
}
#define FAU(x) __float_as_uint(x)
template <int KB>
__device__ __forceinline__ void mma_tile_frag(const float* __restrict__ sA,
                                              const float* __restrict__ sB,
                                              int wm, int wn, int lane,
                                              float4 acc[2][4]) {
    const float4* A = (const float4*)sA;
    const float4* B = (const float4*)sB;
#pragma unroll
    for (int kk = 0; kk < KB; kk++) {
        float4 a0 = A[((2 * wm)     * KB + kk) * 32 + lane];
        float4 a1 = A[((2 * wm + 1) * KB + kk) * 32 + lane];
        float4 b0 = B[((2 * wn)     * KB + kk) * 32 + lane];
        float4 b1 = B[((2 * wn + 1) * KB + kk) * 32 + lane];
        mma8(acc[0][0], FAU(a0.x), FAU(a0.y), FAU(a0.z), FAU(a0.w), FAU(b0.x), FAU(b0.y));
        mma8(acc[1][0], FAU(a1.x), FAU(a1.y), FAU(a1.z), FAU(a1.w), FAU(b0.x), FAU(b0.y));
        mma8(acc[0][1], FAU(a0.x), FAU(a0.y), FAU(a0.z), FAU(a0.w), FAU(b0.z), FAU(b0.w));
        mma8(acc[1][1], FAU(a1.x), FAU(a1.y), FAU(a1.z), FAU(a1.w), FAU(b0.z), FAU(b0.w));
        mma8(acc[0][2], FAU(a0.x), FAU(a0.y), FAU(a0.z), FAU(a0.w), FAU(b1.x), FAU(b1.y));
        mma8(acc[1][2], FAU(a1.x), FAU(a1.y), FAU(a1.z), FAU(a1.w), FAU(b1.x), FAU(b1.y));
        mma8(acc[0][3], FAU(a0.x), FAU(a0.y), FAU(a0.z), FAU(a0.w), FAU(b1.z), FAU(b1.w));
        mma8(acc[1][3], FAU(a1.x), FAU(a1.y), FAU(a1.z), FAU(a1.w), FAU(b1.z), FAU(b1.w));
    }
}
__device__ __forceinline__ void zacc4(float4 acc[2][4]) {
#pragma unroll
    for (int i = 0; i < 2; i++)
#pragma unroll
        for (int j = 0; j < 4; j++) acc[i][j] = make_float4(0.f, 0.f, 0.f, 0.f);
}

// ---------------- setup ----------------
__global__ void k_hist(const float* __restrict__ xyz, const int* __restrict__ src,
                       const int* __restrict__ dst) {
    int e = blockIdx.x * blockDim.x + threadIdx.x;
    if (e >= NE) return;
    int s = src[e], d = dst[e];
    atomicAdd(&g_cnt_all[d], 1);
    if (edge_r(xyz, s, d) < 8.f) atomicAdd(&g_cnt_live[d], 1);
}

__global__ __launch_bounds__(512) void k_scan() {
    __shared__ int part[512];
    __shared__ int total;
    int t = threadIdx.x;
    const int CH = (NA + 511) / 512;
#pragma unroll 1
    for (int pass = 0; pass < 2; pass++) {
        int* cnt = pass ? g_cnt_live : g_cnt_all;
        int* off = pass ? g_off_live : g_off_all;
        int lo = t * CH, hi = min(lo + CH, NA);
        int s = 0;
        for (int i = lo; i < hi; i++) s += cnt[i];
        part[t] = s;
        __syncthreads();
        if (t == 0) {
            int run = 0;
            for (int i = 0; i < 512; i++) { int v = part[i]; part[i] = run; run += v; }
            total = run;
        }
        __syncthreads();
        int run = part[t];
        for (int i = lo; i < hi; i++) { int v = cnt[i]; off[i] = run; run += v; cnt[i] = 0; }
        if (pass == 1 && t == 0) g_nlive = total;
        __syncthreads();
    }
}

__global__ void k_scatter(const float* __restrict__ xyz, const int* __restrict__ src,
                          const int* __restrict__ dst) {
    int e = blockIdx.x * blockDim.x + threadIdx.x;
    if (e >= NE) return;
    int s = src[e], d = dst[e];
    int pos = g_off_all[d] + atomicAdd(&g_cnt_all[d], 1);
    g_ssrc[pos] = s;
    g_sdst[pos] = d;
    float r = edge_r(xyz, s, d);
    if (r < 8.f) {
        int lp = g_off_live[d] + atomicAdd(&g_cnt_live[d], 1);
        g_lsrc[lp] = s; g_lpos[lp] = pos; g_lr[lp] = r;
    }
}

__global__ void k_embed(const float* __restrict__ emb, const int* __restrict__ z,
                        float* __restrict__ x) {
    int i = blockIdx.x * blockDim.x + threadIdx.x;
    if (i < NA * DD) {
        int n = i >> 7, d = i & 127;
        x[i] = emb[z[n] * DD + d];
    }
}

// ---------------- Wfil table build: rows = grid points r = li*(8/NTAB) ----------------
__global__ __launch_bounds__(512) void k_tab(
    const float* __restrict__ Wl, const float* __restrict__ bl,
    const float* __restrict__ W1f, const float* __restrict__ b1f,
    const float* __restrict__ W2f, const float* __restrict__ b2f) {
    extern __shared__ float sm[];
    float* sf   = sm;
    float* sg   = sf + 4096;
    float* sW1t = sg + 16384;
    float* sWlt = sW1t + 4096;
    float* sW2t = sWlt + 4096;
    float* sC   = sW2t + 16384;       // 128
    float* sb1  = sC + 128;
    float* sb   = sb1 + 128;

    int tid = threadIdx.x, lane = tid & 31, w = tid >> 5;
    int wm = w & 3, wn = w >> 2;
    int g = lane >> 2, t4 = lane & 3;

    for (int i = tid; i < 32 * 128; i += 512) {
        int k = i >> 7, n = i & 127;
        sW1t[fragB_idx<4>(k, n)] = f2tff(W1f[i]);
        sWlt[fragB_idx<4>(k, n)] = f2tff(Wl[i]);
    }
    for (int i = tid; i < 128 * 128; i += 512) {
        int k = i >> 7, n = i & 127;
        sW2t[fragB_idx<16>(k, n)] = f2tff(W2f[i]);
    }
    if (tid < 128) { sb1[tid] = b1f[tid]; sb[tid] = bl[tid] + b2f[tid]; }

    const int NROWS = NTAB + 1;
    for (int tt = blockIdx.x; tt * 128 < NROWS; tt += gridDim.x) {
        if (tid < 128) {
            int li = tt * 128 + tid;
            float r = (float)li * (8.f / NTAB);
            sC[tid] = (r < 8.f) ? (0.5f * (cospif(r * 0.125f) + 1.f)) : 0.f;
        }
        __syncthreads();
        {
            int el = tid >> 2, kb = (tid & 3) * 8;
            float r = (float)(tt * 128 + el) * (8.f / NTAB);
#pragma unroll
            for (int q = 0; q < 8; q++) {
                int k = kb + q;
                float off = (float)k * (8.f / 31.f);
                float u = (r - off) * (31.f / 8.f);
                sf[fragA_idx<4>(el, k)] = f2tff(__expf(-0.5f * u * u));
            }
        }
        __syncthreads();

        float4 acc[2][4];
        zacc4(acc);
        mma_tile_frag<4>(sf, sW1t, wm, wn, lane, acc);
        __syncthreads();
#pragma unroll
        for (int mi = 0; mi < 2; mi++) {
            int r = 32 * wm + 16 * mi + g;
#pragma unroll
            for (int jl = 0; jl < 4; jl++) {
                int c = 32 * wn + 8 * jl + 2 * t4;
                float4 d = acc[mi][jl];
                float v0 = d.x + sb1[c], v1 = d.y + sb1[c + 1];
                float v2 = d.z + sb1[c], v3 = d.w + sb1[c + 1];
                sg[fragA_idx<16>(r, c)]         = f2tff(v0 / (1.f + __expf(-v0)));
                sg[fragA_idx<16>(r, c + 1)]     = f2tff(v1 / (1.f + __expf(-v1)));
                sg[fragA_idx<16>(r + 8, c)]     = f2tff(v2 / (1.f + __expf(-v2)));
                sg[fragA_idx<16>(r + 8, c + 1)] = f2tff(v3 / (1.f + __expf(-v3)));
            }
        }
        __syncthreads();

        zacc4(acc);
        mma_tile_frag<4>(sf, sWlt, wm, wn, lane, acc);
        mma_tile_frag<16>(sg, sW2t, wm, wn, lane, acc);

#pragma unroll
        for (int mi = 0; mi < 2; mi++) {
            int r = 32 * wm + 16 * mi + g;
#pragma unroll
            for (int jl = 0; jl < 4; jl++) {
                int c = 32 * wn + 8 * jl + 2 * t4;
                float4 d = acc[mi][jl];
                int li0 = tt * 128 + r, li1 = li0 + 8;
                if (li0 < NROWS) {
                    float Cv = sC[r];
                    *(float2*)(g_tab + (size_t)li0 * 128 + c) =
                        make_float2((d.x + sb[c]) * Cv, (d.y + sb[c + 1]) * Cv);
                }
                if (li1 < NROWS) {
                    float Cv = sC[r + 8];
                    *(float2*)(g_tab + (size_t)li1 * 128 + c) =
                        make_float2((d.z + sb[c]) * Cv, (d.w + sb[c + 1]) * Cv);
                }
            }
        }
        __syncthreads();
    }
}

// ---------------- fused out+hqk: x += msg@Wo; h = x+te; Q = h@Wq; K = h@Wk ----------------
__global__ __launch_bounds__(512) void k_oqk(float* __restrict__ x,
                                             const float* __restrict__ te,
                                             const float* __restrict__ Wo,
                                             const float* __restrict__ Wq,
                                             const float* __restrict__ Wk, int it) {
    extern __shared__ float sm[];
    float* sA = sm;
    float* sB = sm + 16384;
    int tid = threadIdx.x, lane = tid & 31, w = tid >> 5;
    int wm = w & 3, wn = w >> 2;
    int g = lane >> 2, t4 = lane & 3;
    int n0 = blockIdx.x * 128;

    float4 acc[2][4];
    zacc4(acc);
    if (it > 0) {
        for (int i = tid; i < 128 * 128; i += 512) {
            int r = i >> 7, c = i & 127, n = n0 + r;
            sA[fragA_idx<16>(r, c)] = (n < NA) ? f2tff(g_msg[(size_t)n * 128 + c]) : 0.f;
        }
        for (int i = tid; i < 128 * 128; i += 512) {
            int k = i >> 7, n = i & 127;
            sB[fragB_idx<16>(k, n)] = f2tff(Wo[i]);
        }
        __syncthreads();
        mma_tile_frag<16>(sA, sB, wm, wn, lane, acc);
        __syncthreads();
    }
#pragma unroll
    for (int mi = 0; mi < 2; mi++) {
        int r = 32 * wm + 16 * mi + g;
#pragma unroll
        for (int jl = 0; jl < 4; jl++) {
            int c = 32 * wn + 8 * jl + 2 * t4;
            float4 d = acc[mi][jl];
            float te0 = te[it * 128 + c], te1 = te[it * 128 + c + 1];
            int n1 = n0 + r, n2 = n1 + 8;
            float h00 = 0.f, h01 = 0.f, h10 = 0.f, h11 = 0.f;
            if (n1 < NA) {
                float2 xv = *(float2*)(x + (size_t)n1 * 128 + c);
                xv.x += d.x; xv.y += d.y;
                *(float2*)(x + (size_t)n1 * 128 + c) = xv;
                h00 = xv.x + te0; h01 = xv.y + te1;
                *(float2*)(g_h + (size_t)n1 * 128 + c) = make_float2(h00, h01);
            }
            if (n2 < NA) {
                float2 xv = *(float2*)(x + (size_t)n2 * 128 + c);
                xv.x += d.z; xv.y += d.w;
                *(float2*)(x + (size_t)n2 * 128 + c) = xv;
                h10 = xv.x + te0; h11 = xv.y + te1;
                *(float2*)(g_h + (size_t)n2 * 128 + c) = make_float2(h10, h11);
            }
            sA[fragA_idx<16>(r, c)]         = f2tff(h00);
            sA[fragA_idx<16>(r, c + 1)]     = f2tff(h01);
            sA[fragA_idx<16>(r + 8, c)]     = f2tff(h10);
            sA[fragA_idx<16>(r + 8, c + 1)] = f2tff(h11);
        }
    }
    for (int i = tid; i < 128 * 128; i += 512) {
        int k = i >> 7, n = i & 127;
        sB[fragB_idx<16>(k, n)] = f2tff(Wq[i]);
    }
    __syncthreads();
    zacc4(acc);
    mma_tile_frag<16>(sA, sB, wm, wn, lane, acc);
#pragma unroll
    for (int mi = 0; mi < 2; mi++) {
        int r = 32 * wm + 16 * mi + g;
#pragma unroll
        for (int jl = 0; jl < 4; jl++) {
            int c = 32 * wn + 8 * jl + 2 * t4;
            float4 d = acc[mi][jl];
            int n1 = n0 + r, n2 = n1 + 8;
            if (n1 < NA) *(float2*)(g_Q + (size_t)n1 * 128 + c) = make_float2(d.x, d.y);
            if (n2 < NA) *(float2*)(g_Q + (size_t)n2 * 128 + c) = make_float2(d.z, d.w);
        }
    }
    __syncthreads();
    for (int i = tid; i < 128 * 128; i += 512) {
        int k = i >> 7, n = i & 127;
        sB[fragB_idx<16>(k, n)] = f2tff(Wk[i]);
    }
    __syncthreads();
    zacc4(acc);
    mma_tile_frag<16>(sA, sB, wm, wn, lane, acc);
#pragma unroll
    for (int mi = 0; mi < 2; mi++) {
        int r = 32 * wm + 16 * mi + g;
#pragma unroll
        for (int jl = 0; jl < 4; jl++) {
            int c = 32 * wn + 8 * jl + 2 * t4;
            float4 d = acc[mi][jl];
            int n1 = n0 + r, n2 = n1 + 8;
            if (n1 < NA) *(float2*)(g_K + (size_t)n1 * 128 + c) = make_float2(d.x, d.y);
            if (n2 < NA) *(float2*)(g_K + (size_t)n2 * 128 + c) = make_float2(d.z, d.w);
        }
    }
}

// ---------------- fused attention: softmax + per-atom U aggregation (R10 winner) ----------------
__global__ __launch_bounds__(256) void k_attn() {
    int warp = (blockIdx.x * blockDim.x + threadIdx.x) >> 5;
    int lane = threadIdx.x & 31;
    if (warp >= NA) return;
    int d = warp;
    int beg = g_off_all[d], cnt = g_cnt_all[d];

    float acc[8][4];
#pragma unroll
    for (int b = 0; b < 8; b++)
#pragma unroll
        for (int j = 0; j < 4; j++) acc[b][j] = 0.f;

    if (cnt > 0) {
        // pass 1: scores + online per-head max/denominator
        float4 q = *(const float4*)(g_Q + (size_t)d * 128 + lane * 4);
        float m = -1e30f, den = 0.f;
        for (int i = 0; i < cnt; i++) {
            int e = beg + i;
            int s = g_ssrc[e];
            float4 kv = *(const float4*)(g_K + (size_t)s * 128 + lane * 4);
            float p = q.x * kv.x + q.y * kv.y + q.z * kv.z + q.w * kv.w;
            p += __shfl_xor_sync(0xffffffffu, p, 1);
            p += __shfl_xor_sync(0xffffffffu, p, 2);
            p *= 0.25f;
            float mn = fmaxf(m, p);
            den = den * __expf(m - mn) + __expf(p - mn);
            m = mn;
            float t = __shfl_sync(0xffffffffu, p, (lane & 7) * 4);
            if (lane < 8) g_s[(size_t)e * 8 + lane] = t;
        }
        __syncwarp();
        // pass 2: normalize a into g_s
        float mh  = __shfl_sync(0xffffffffu, m,   (lane & 7) * 4);
        float dh  = __shfl_sync(0xffffffffu, den, (lane & 7) * 4);
        float inv = 1.f / (dh + 1e-12f);
        int h = lane & 7, eo = lane >> 3;
        for (int base = 0; base < cnt; base += 4) {
            int i = base + eo;
            if (i < cnt) {
                size_t o = (size_t)(beg + i) * 8 + h;
                g_s[o] = __expf(g_s[o] - mh) * inv;
            }
        }
        __syncwarp();
        // pass 3: U[d][b][dim] = sum over live edges of a_b * (h[src] * F(r))
        int lbeg = g_off_live[d], lcnt = g_cnt_live[d];
        for (int i = 0; i < lcnt; i++) {
            int lp = lbeg + i;
            int e = g_lpos[lp];
            int s = g_lsrc[lp];
            float rr = g_lr[lp];
            float t = rr * ((float)NTAB / 8.f);
            int i0 = (int)t;
            float fr = t - (float)i0;
            float4 a0 = *(const float4*)(g_s + (size_t)e * 8);
            float4 a1 = *(const float4*)(g_s + (size_t)e * 8 + 4);
            float4 hv = *(const float4*)(g_h + (size_t)s * 128 + lane * 4);
            const float* tp = g_tab + (size_t)i0 * 128 + lane * 4;
            float4 w0 = *(const float4*)tp;
            float4 w1 = *(const float4*)(tp + 128);
            float wx = w0.x + fr * (w1.x - w0.x);
            float wy = w0.y + fr * (w1.y - w0.y);
            float wz = w0.z + fr * (w1.z - w0.z);
            float ww = w0.w + fr * (w1.w - w0.w);
            float u0 = hv.x * wx, u1 = hv.y * wy;
            float u2 = hv.z * wz, u3 = hv.w * ww;
            float ab[8] = {a0.x, a0.y, a0.z, a0.w, a1.x, a1.y, a1.z, a1.w};
#pragma unroll
            for (int b = 0; b < 8; b++) {
                acc[b][0] += ab[b] * u0; acc[b][1] += ab[b] * u1;
                acc[b][2] += ab[b] * u2; acc[b][3] += ab[b] * u3;
            }
        }
    }
    float* up = g_U + (size_t)d * 1024 + lane * 4;
#pragma unroll
    for (int b = 0; b < 8; b++)
        *(float4*)(up + b * 128) = make_float4(acc[b][0], acc[b][1], acc[b][2], acc[b][3]);
}

// ---------------- ugemm: msg[:, 16b:16b+16] = U[:, b, :] @ Wv[:, 16b:16b+16] ----------------
__global__ __launch_bounds__(256) void k_ugemm(const float* __restrict__ Wv) {
    extern __shared__ float sm[];
    float* sU = sm;            // 128 atoms x 128 dims (64 KB)
    float* sW = sm + 16384;    // 128 x 16 (8 KB)
    int b = blockIdx.y, n0 = blockIdx.x * 128, tid = threadIdx.x;

    for (int i = tid; i < 128 * 16; i += 256) {
        int k = i >> 4, c = i & 15;
        sW[i] = Wv[k * 128 + b * 16 + c];
    }
    for (int i = tid; i < 128 * 32; i += 256) {
        int r = i >> 5, kq = i & 31;
        int n = n0 + r;
        float4 v = (n < NA) ? *(const float4*)(g_U + (size_t)n * 1024 + b * 128 + kq * 4)
                            : make_float4(0.f, 0.f, 0.f, 0.f);
        *(float4*)(sU + r * 128 + kq * 4) = v;
    }
    __syncthreads();

    int col = tid & 15, rg = tid >> 4;   // rows rg*8..rg*8+7
    float acc[8] = {0.f, 0.f, 0.f, 0.f, 0.f, 0.f, 0.f, 0.f};
#pragma unroll 4
    for (int k4 = 0; k4 < 128; k4 += 4) {
        float bw[4];
#pragma unroll
        for (int q = 0; q < 4; q++) bw[q] = sW[(k4 + q) * 16 + col];
#pragma unroll
        for (int j = 0; j < 8; j++) {
            float4 av = *(const float4*)(sU + (rg * 8 + j) * 128 + k4);
            acc[j] += av.x * bw[0] + av.y * bw[1] + av.z * bw[2] + av.w * bw[3];
        }
    }
#pragma unroll
    for (int j = 0; j < 8; j++) {
        int n = n0 + rg * 8 + j;
        if (n < NA) g_msg[(size_t)n * 128 + b * 16 + col] = acc[j];
    }
}

// ---------------- final: x += msg @ Wo; reset counters for next call ----------------
__global__ __launch_bounds__(512) void k_out(float* __restrict__ x,
                                             const float* __restrict__ Wo) {
    extern __shared__ float sm[];
    float* sA  = sm;
    float* sBt = sA + 16384;
    int tid = threadIdx.x, lane = tid & 31, w = tid >> 5;
    int wm = w & 3, wn = w >> 2;
    int g = lane >> 2, t4 = lane & 3;
    int n0 = blockIdx.x * 128;

    int gidx = blockIdx.x * 512 + tid;
    if (gidx < NA) { g_cnt_all[gidx] = 0; g_cnt_live[gidx] = 0; }

    for (int i = tid; i < 128 * 128; i += 512) {
        int r = i >> 7, c = i & 127;
        int n = n0 + r;
        sA[fragA_idx<16>(r, c)] = (n < NA) ? f2tff(g_msg[(size_t)n * 128 + c]) : 0.f;
    }
    for (int i = tid; i < 128 * 128; i += 512) {
        int k = i >> 7, n = i & 127;
        sBt[fragB_idx<16>(k, n)] = f2tff(Wo[i]);
    }
    __syncthreads();

    float4 acc[2][4];
    zacc4(acc);
    mma_tile_frag<16>(sA, sBt, wm, wn, lane, acc);
#pragma unroll
    for (int mi = 0; mi < 2; mi++) {
        int r = 32 * wm + 16 * mi + g;
#pragma unroll
        for (int jl = 0; jl < 4; jl++) {
            int c = 32 * wn + 8 * jl + 2 * t4;
            float4 d = acc[mi][jl];
            int n1 = n0 + r, n2 = n1 + 8;
            if (n1 < NA) {
                float2 o = *(float2*)(x + (size_t)n1 * 128 + c);
                o.x += d.x; o.y += d.y;
                *(float2*)(x + (size_t)n1 * 128 + c) = o;
            }
            if (n2 < NA) {
                float2 o = *(float2*)(x + (size_t)n2 * 128 + c);
                o.x += d.z; o.y += d.w;
                *(float2*)(x + (size_t)n2 * 128 + c) = o;
            }
        }
    }
}

// ---------------- launch ----------------
extern "C" void kernel_launch(void* const* d_in, const int* in_sizes, int n_in,
                              void* d_out, int out_size) {
    const float* xyz = (const float*)d_in[0];
    const float* emb = (const float*)d_in[1];
    const float* te  = (const float*)d_in[2];
    const float* Wl  = (const float*)d_in[3];
    const float* bl  = (const float*)d_in[4];
    const float* W1f = (const float*)d_in[5];
    const float* b1f = (const float*)d_in[6];
    const float* W2f = (const float*)d_in[7];
    const float* b2f = (const float*)d_in[8];
    const float* Wq  = (const float*)d_in[9];
    const float* Wk  = (const float*)d_in[10];
    const float* Wv  = (const float*)d_in[11];
    const float* Wo  = (const float*)d_in[12];
    const int*   z   = (const int*)d_in[13];
    const int*   src = (const int*)d_in[14];
    const int*   dst = (const int*)d_in[15];
    float* x = (float*)d_out;

    const int SM_TAB   = (4096 + 16384 + 4096 + 4096 + 16384 + 3 * 128) * 4;
    const int SM_OQK   = (2 * 16384) * 4;
    const int SM_UGEMM = (16384 + 128 * 16) * 4;   // 73728
    const int SM_OUT   = (2 * 16384) * 4;

    cudaFuncSetAttribute(k_tab,   cudaFuncAttributeMaxDynamicSharedMemorySize, SM_TAB);
    cudaFuncSetAttribute(k_oqk,   cudaFuncAttributeMaxDynamicSharedMemorySize, SM_OQK);
    cudaFuncSetAttribute(k_ugemm, cudaFuncAttributeMaxDynamicSharedMemorySize, SM_UGEMM);
    cudaFuncSetAttribute(k_out,   cudaFuncAttributeMaxDynamicSharedMemorySize, SM_OUT);

    k_hist<<<NE / 256, 256>>>(xyz, src, dst);
    k_scan<<<1, 512>>>();
    k_scatter<<<NE / 256, 256>>>(xyz, src, dst);
    k_tab<<<(NTAB + 1 + 127) / 128, 512, SM_TAB>>>(Wl, bl, W1f, b1f, W2f, b2f);
    k_embed<<<(NA * DD + 255) / 256, 256>>>(emb, z, x);

    const int NBLK = (NA + 127) / 128;   // 157
    dim3 ug(NBLK, 8);
    for (int it = 0; it < NIT; it++) {
        k_oqk<<<NBLK, 512, SM_OQK>>>(x, te, Wo, Wq, Wk, it);
        k_attn<<<(NA * 32 + 255) / 256, 256>>>();
        k_ugemm<<<ug, 256, SM_UGEMM>>>(Wv);
    }
    k_out<<<NBLK, 512, SM_OUT>>>(x, Wo);
}

// round 14
// speedup vs baseline: 1.4557x; 1.0398x over previous
#include <cuda_runtime.h>
#include <cuda_fp16.h>
#include <math.h>
#include <stdint.h>

#define NA 20000
#define NE 640000
#define DD 128
#define GG 32
#define HH 8
#define NIT 4
#define NSM 148
#define NTAB 4096

// ---------------- device scratch ----------------
__device__ float    g_tab[(NTAB + 1) * DD];   // Wfil lookup table over r in [0,8]
__device__ int      g_ssrc[NE];     // src, sorted by dst
__device__ int      g_lsrc[NE];     // live subset, sorted by dst
__device__ int      g_lpos[NE];
__device__ float    g_lr[NE];       // live edge distance
__device__ int      g_cnt_all[NA];  // statically zero; re-zeroed by final k_out
__device__ int      g_cnt_live[NA];
__device__ int      g_off_all[NA];
__device__ int      g_off_live[NA];
__device__ int      g_nlive;
__device__ float    g_h[NA * DD];
__device__ float    g_Q[NA * DD];
__device__ float    g_K[NA * DD];
__device__ float    g_s[NE * HH];
__device__ __half   g_U[(size_t)NA * 1024];   // per-atom [8 heads][128 dims], fp16
__device__ float    g_msg[NA * DD];

__device__ __forceinline__ float edge_r(const float* xyz, int s, int d) {
    float dx = xyz[3 * s]     - xyz[3 * d];
    float dy = xyz[3 * s + 1] - xyz[3 * d + 1];
    float dz = xyz[3 * s + 2] - xyz[3 * d + 2];
    return sqrtf(dx * dx + dy * dy + dz * dz + 1e-12f);
}

// ---------------- tf32 MMA core with fragment-major smem ----------------
__device__ __forceinline__ uint32_t f2tf(float f) {
    uint32_t u;
    asm("cvt.rna.tf32.f32 %0, %1;" : "=r"(u) : "f"(f));
    return u;
}
__device__ __forceinline__ float f2tff(float f) { return __uint_as_float(f2tf(f)); }

__device__ __forceinline__ void mma8(float4& d,
                                     uint32_t a0, uint32_t a1, uint32_t a2, uint32_t a3,
                                     uint32_t b0, uint32_t b1) {
    asm volatile(
        "mma.sync.aligned.m16n8k8.row.col.f32.tf32.tf32.f32 "
        "{%0,%1,%2,%3},{%4,%5,%6,%7},{%8,%9},{%0,%1,%2,%3};"
        : "+f"(d.x), "+f"(d.y), "+f"(d.z), "+f"(d.w)
        : "r"(a0), "r"(a1), "r"(a2), "r"(a3), "r"(b0), "r"(b1));
}
template <int KB>
__device__ __forceinline__ int fragA_idx(int r, int k) {
    return (((r >> 4) * KB + (k >> 3)) << 7) + (((r & 7) * 4 + (k & 3)) << 2)
         + ((r >> 3) & 1) + (((k >> 2) & 1) << 1);
}
template <int KB>
__device__ __forceinline__ int fragB_idx(int k, int n) {
    return (((n >> 4) * KB + (k >> 3)) << 7) + (((n & 7) * 4 + (k & 3)) << 2)
         + (((n >> 3) & 1) << 1) + ((k >> 2) & 1);
}
#define FAU(x) __float_as_uint(x)
template <int KB>
__device__ __forceinline__ void mma_tile_frag(const float* __restrict__ sA,
                                              const float* __restrict__ sB,
                                              int wm, int wn, int lane,
                                              float4 acc[2][4]) {
    const float4* A = (const float4*)sA;
    const float4* B = (const float4*)sB;
#pragma unroll
    for (int kk = 0; kk < KB; kk++) {
        float4 a0 = A[((2 * wm)     * KB + kk) * 32 + lane];
        float4 a1 = A[((2 * wm + 1) * KB + kk) * 32 + lane];
        float4 b0 = B[((2 * wn)     * KB + kk) * 32 + lane];
        float4 b1 = B[((2 * wn + 1) * KB + kk) * 32 + lane];
        mma8(acc[0][0], FAU(a0.x), FAU(a0.y), FAU(a0.z), FAU(a0.w), FAU(b0.x), FAU(b0.y));
        mma8(acc[1][0], FAU(a1.x), FAU(a1.y), FAU(a1.z), FAU(a1.w), FAU(b0.x), FAU(b0.y));
        mma8(acc[0][1], FAU(a0.x), FAU(a0.y), FAU(a0.z), FAU(a0.w), FAU(b0.z), FAU(b0.w));
        mma8(acc[1][1], FAU(a1.x), FAU(a1.y), FAU(a1.z), FAU(a1.w), FAU(b0.z), FAU(b0.w));
        mma8(acc[0][2], FAU(a0.x), FAU(a0.y), FAU(a0.z), FAU(a0.w), FAU(b1.x), FAU(b1.y));
        mma8(acc[1][2], FAU(a1.x), FAU(a1.y), FAU(a1.z), FAU(a1.w), FAU(b1.x), FAU(b1.y));
        mma8(acc[0][3], FAU(a0.x), FAU(a0.y), FAU(a0.z), FAU(a0.w), FAU(b1.z), FAU(b1.w));
        mma8(acc[1][3], FAU(a1.x), FAU(a1.y), FAU(a1.z), FAU(a1.w), FAU(b1.z), FAU(b1.w));
    }
}
__device__ __forceinline__ void zacc4(float4 acc[2][4]) {
#pragma unroll
    for (int i = 0; i < 2; i++)
#pragma unroll
        for (int j = 0; j < 4; j++) acc[i][j] = make_float4(0.f, 0.f, 0.f, 0.f);
}

// ---------------- setup ----------------
__global__ void k_hist(const float* __restrict__ xyz, const int* __restrict__ src,
                       const int* __restrict__ dst) {
    int e = blockIdx.x * blockDim.x + threadIdx.x;
    if (e >= NE) return;
    int s = src[e], d = dst[e];
    atomicAdd(&g_cnt_all[d], 1);
    if (edge_r(xyz, s, d) < 8.f) atomicAdd(&g_cnt_live[d], 1);
}

__global__ __launch_bounds__(512) void k_scan() {
    __shared__ int part[512];
    __shared__ int total;
    int t = threadIdx.x;
    const int CH = (NA + 511) / 512;
#pragma unroll 1
    for (int pass = 0; pass < 2; pass++) {
        int* cnt = pass ? g_cnt_live : g_cnt_all;
        int* off = pass ? g_off_live : g_off_all;
        int lo = t * CH, hi = min(lo + CH, NA);
        int s = 0;
        for (int i = lo; i < hi; i++) s += cnt[i];
        part[t] = s;
        __syncthreads();
        if (t == 0) {
            int run = 0;
            for (int i = 0; i < 512; i++) { int v = part[i]; part[i] = run; run += v; }
            total = run;
        }
        __syncthreads();
        int run = part[t];
        for (int i = lo; i < hi; i++) { int v = cnt[i]; off[i] = run; run += v; cnt[i] = 0; }
        if (pass == 1 && t == 0) g_nlive = total;
        __syncthreads();
    }
}

__global__ void k_scatter(const float* __restrict__ xyz, const int* __restrict__ src,
                          const int* __restrict__ dst) {
    int e = blockIdx.x * blockDim.x + threadIdx.x;
    if (e >= NE) return;
    int s = src[e], d = dst[e];
    int pos = g_off_all[d] + atomicAdd(&g_cnt_all[d], 1);
    g_ssrc[pos] = s;
    float r = edge_r(xyz, s, d);
    if (r < 8.f) {
        int lp = g_off_live[d] + atomicAdd(&g_cnt_live[d], 1);
        g_lsrc[lp] = s; g_lpos[lp] = pos; g_lr[lp] = r;
    }
}

__global__ void k_embed(const float* __restrict__ emb, const int* __restrict__ z,
                        float* __restrict__ x) {
    int i = blockIdx.x * blockDim.x + threadIdx.x;
    if (i < NA * DD) {
        int n = i >> 7, d = i & 127;
        x[i] = emb[z[n] * DD + d];
    }
}

// ---------------- Wfil table build: rows = grid points r = li*(8/NTAB) ----------------
__global__ __launch_bounds__(512) void k_tab(
    const float* __restrict__ Wl, const float* __restrict__ bl,
    const float* __restrict__ W1f, const float* __restrict__ b1f,
    const float* __restrict__ W2f, const float* __restrict__ b2f) {
    extern __shared__ float sm[];
    float* sf   = sm;
    float* sg   = sf + 4096;
    float* sW1t = sg + 16384;
    float* sWlt = sW1t + 4096;
    float* sW2t = sWlt + 4096;
    float* sC   = sW2t + 16384;       // 128
    float* sb1  = sC + 128;
    float* sb   = sb1 + 128;

    int tid = threadIdx.x, lane = tid & 31, w = tid >> 5;
    int wm = w & 3, wn = w >> 2;
    int g = lane >> 2, t4 = lane & 3;

    for (int i = tid; i < 32 * 128; i += 512) {
        int k = i >> 7, n = i & 127;
        sW1t[fragB_idx<4>(k, n)] = f2tff(W1f[i]);
        sWlt[fragB_idx<4>(k, n)] = f2tff(Wl[i]);
    }
    for (int i = tid; i < 128 * 128; i += 512) {
        int k = i >> 7, n = i & 127;
        sW2t[fragB_idx<16>(k, n)] = f2tff(W2f[i]);
    }
    if (tid < 128) { sb1[tid] = b1f[tid]; sb[tid] = bl[tid] + b2f[tid]; }

    const int NROWS = NTAB + 1;
    for (int tt = blockIdx.x; tt * 128 < NROWS; tt += gridDim.x) {
        if (tid < 128) {
            int li = tt * 128 + tid;
            float r = (float)li * (8.f / NTAB);
            sC[tid] = (r < 8.f) ? (0.5f * (cospif(r * 0.125f) + 1.f)) : 0.f;
        }
        __syncthreads();
        {
            int el = tid >> 2, kb = (tid & 3) * 8;
            float r = (float)(tt * 128 + el) * (8.f / NTAB);
#pragma unroll
            for (int q = 0; q < 8; q++) {
                int k = kb + q;
                float off = (float)k * (8.f / 31.f);
                float u = (r - off) * (31.f / 8.f);
                sf[fragA_idx<4>(el, k)] = f2tff(__expf(-0.5f * u * u));
            }
        }
        __syncthreads();

        float4 acc[2][4];
        zacc4(acc);
        mma_tile_frag<4>(sf, sW1t, wm, wn, lane, acc);
        __syncthreads();
#pragma unroll
        for (int mi = 0; mi < 2; mi++) {
            int r = 32 * wm + 16 * mi + g;
#pragma unroll
            for (int jl = 0; jl < 4; jl++) {
                int c = 32 * wn + 8 * jl + 2 * t4;
                float4 d = acc[mi][jl];
                float v0 = d.x + sb1[c], v1 = d.y + sb1[c + 1];
                float v2 = d.z + sb1[c], v3 = d.w + sb1[c + 1];
                sg[fragA_idx<16>(r, c)]         = f2tff(v0 / (1.f + __expf(-v0)));
                sg[fragA_idx<16>(r, c + 1)]     = f2tff(v1 / (1.f + __expf(-v1)));
                sg[fragA_idx<16>(r + 8, c)]     = f2tff(v2 / (1.f + __expf(-v2)));
                sg[fragA_idx<16>(r + 8, c + 1)] = f2tff(v3 / (1.f + __expf(-v3)));
            }
        }
        __syncthreads();

        zacc4(acc);
        mma_tile_frag<4>(sf, sWlt, wm, wn, lane, acc);
        mma_tile_frag<16>(sg, sW2t, wm, wn, lane, acc);

#pragma unroll
        for (int mi = 0; mi < 2; mi++) {
            int r = 32 * wm + 16 * mi + g;
#pragma unroll
            for (int jl = 0; jl < 4; jl++) {
                int c = 32 * wn + 8 * jl + 2 * t4;
                float4 d = acc[mi][jl];
                int li0 = tt * 128 + r, li1 = li0 + 8;
                if (li0 < NROWS) {
                    float Cv = sC[r];
                    *(float2*)(g_tab + (size_t)li0 * 128 + c) =
                        make_float2((d.x + sb[c]) * Cv, (d.y + sb[c + 1]) * Cv);
                }
                if (li1 < NROWS) {
                    float Cv = sC[r + 8];
                    *(float2*)(g_tab + (size_t)li1 * 128 + c) =
                        make_float2((d.z + sb[c]) * Cv, (d.w + sb[c + 1]) * Cv);
                }
            }
        }
        __syncthreads();
    }
}

// ---------------- fused out+hqk: x += msg@Wo; h = x+te; Q = h@Wq; K = h@Wk ----------------
__global__ __launch_bounds__(512) void k_oqk(float* __restrict__ x,
                                             const float* __restrict__ te,
                                             const float* __restrict__ Wo,
                                             const float* __restrict__ Wq,
                                             const float* __restrict__ Wk, int it) {
    extern __shared__ float sm[];
    float* sA = sm;
    float* sB = sm + 16384;
    int tid = threadIdx.x, lane = tid & 31, w = tid >> 5;
    int wm = w & 3, wn = w >> 2;
    int g = lane >> 2, t4 = lane & 3;
    int n0 = blockIdx.x * 128;

    float4 acc[2][4];
    zacc4(acc);
    if (it > 0) {
        for (int i = tid; i < 128 * 128; i += 512) {
            int r = i >> 7, c = i & 127, n = n0 + r;
            sA[fragA_idx<16>(r, c)] = (n < NA) ? f2tff(g_msg[(size_t)n * 128 + c]) : 0.f;
        }
        for (int i = tid; i < 128 * 128; i += 512) {
            int k = i >> 7, n = i & 127;
            sB[fragB_idx<16>(k, n)] = f2tff(Wo[i]);
        }
        __syncthreads();
        mma_tile_frag<16>(sA, sB, wm, wn, lane, acc);
        __syncthreads();
    }
#pragma unroll
    for (int mi = 0; mi < 2; mi++) {
        int r = 32 * wm + 16 * mi + g;
#pragma unroll
        for (int jl = 0; jl < 4; jl++) {
            int c = 32 * wn + 8 * jl + 2 * t4;
            float4 d = acc[mi][jl];
            float te0 = te[it * 128 + c], te1 = te[it * 128 + c + 1];
            int n1 = n0 + r, n2 = n1 + 8;
            float h00 = 0.f, h01 = 0.f, h10 = 0.f, h11 = 0.f;
            if (n1 < NA) {
                float2 xv = *(float2*)(x + (size_t)n1 * 128 + c);
                xv.x += d.x; xv.y += d.y;
                *(float2*)(x + (size_t)n1 * 128 + c) = xv;
                h00 = xv.x + te0; h01 = xv.y + te1;
                *(float2*)(g_h + (size_t)n1 * 128 + c) = make_float2(h00, h01);
            }
            if (n2 < NA) {
                float2 xv = *(float2*)(x + (size_t)n2 * 128 + c);
                xv.x += d.z; xv.y += d.w;
                *(float2*)(x + (size_t)n2 * 128 + c) = xv;
                h10 = xv.x + te0; h11 = xv.y + te1;
                *(float2*)(g_h + (size_t)n2 * 128 + c) = make_float2(h10, h11);
            }
            sA[fragA_idx<16>(r, c)]         = f2tff(h00);
            sA[fragA_idx<16>(r, c + 1)]     = f2tff(h01);
            sA[fragA_idx<16>(r + 8, c)]     = f2tff(h10);
            sA[fragA_idx<16>(r + 8, c + 1)] = f2tff(h11);
        }
    }
    for (int i = tid; i < 128 * 128; i += 512) {
        int k = i >> 7, n = i & 127;
        sB[fragB_idx<16>(k, n)] = f2tff(Wq[i]);
    }
    __syncthreads();
    zacc4(acc);
    mma_tile_frag<16>(sA, sB, wm, wn, lane, acc);
#pragma unroll
    for (int mi = 0; mi < 2; mi++) {
        int r = 32 * wm + 16 * mi + g;
#pragma unroll
        for (int jl = 0; jl < 4; jl++) {
            int c = 32 * wn + 8 * jl + 2 * t4;
            float4 d = acc[mi][jl];
            int n1 = n0 + r, n2 = n1 + 8;
            if (n1 < NA) *(float2*)(g_Q + (size_t)n1 * 128 + c) = make_float2(d.x, d.y);
            if (n2 < NA) *(float2*)(g_Q + (size_t)n2 * 128 + c) = make_float2(d.z, d.w);
        }
    }
    __syncthreads();
    for (int i = tid; i < 128 * 128; i += 512) {
        int k = i >> 7, n = i & 127;
        sB[fragB_idx<16>(k, n)] = f2tff(Wk[i]);
    }
    __syncthreads();
    zacc4(acc);
    mma_tile_frag<16>(sA, sB, wm, wn, lane, acc);
#pragma unroll
    for (int mi = 0; mi < 2; mi++) {
        int r = 32 * wm + 16 * mi + g;
#pragma unroll
        for (int jl = 0; jl < 4; jl++) {
            int c = 32 * wn + 8 * jl + 2 * t4;
            float4 d = acc[mi][jl];
            int n1 = n0 + r, n2 = n1 + 8;
            if (n1 < NA) *(float2*)(g_K + (size_t)n1 * 128 + c) = make_float2(d.x, d.y);
            if (n2 < NA) *(float2*)(g_K + (size_t)n2 * 128 + c) = make_float2(d.z, d.w);
        }
    }
}

// ---------------- fused attention: softmax + per-atom U aggregation ----------------
__global__ __launch_bounds__(256) void k_attn() {
    int warp = (blockIdx.x * blockDim.x + threadIdx.x) >> 5;
    int lane = threadIdx.x & 31;
    if (warp >= NA) return;
    int d = warp;
    int beg = g_off_all[d], cnt = g_cnt_all[d];

    float acc[8][4];
#pragma unroll
    for (int b = 0; b < 8; b++)
#pragma unroll
        for (int j = 0; j < 4; j++) acc[b][j] = 0.f;

    int lbeg = g_off_live[d], lcnt = g_cnt_live[d];
    if (cnt > 0) {
        // pass 1: scores + online per-head max/denominator (ALL edges)
        float4 q = *(const float4*)(g_Q + (size_t)d * 128 + lane * 4);
        float m = -1e30f, den = 0.f;
        for (int i = 0; i < cnt; i++) {
            int e = beg + i;
            int s = g_ssrc[e];
            float4 kv = *(const float4*)(g_K + (size_t)s * 128 + lane * 4);
            float p = q.x * kv.x + q.y * kv.y + q.z * kv.z + q.w * kv.w;
            p += __shfl_xor_sync(0xffffffffu, p, 1);
            p += __shfl_xor_sync(0xffffffffu, p, 2);
            p *= 0.25f;
            float mn = fmaxf(m, p);
            den = den * __expf(m - mn) + __expf(p - mn);
            m = mn;
            float t = __shfl_sync(0xffffffffu, p, (lane & 7) * 4);
            if (lane < 8) g_s[(size_t)e * 8 + lane] = t;
        }
        __syncwarp();
        // pass 2: normalize a into g_s for LIVE edges only
        float mh  = __shfl_sync(0xffffffffu, m,   (lane & 7) * 4);
        float dh  = __shfl_sync(0xffffffffu, den, (lane & 7) * 4);
        float inv = 1.f / (dh + 1e-12f);
        int h = lane & 7, eo = lane >> 3;
        for (int base = 0; base < lcnt; base += 4) {
            int i = base + eo;
            if (i < lcnt) {
                size_t o = (size_t)g_lpos[lbeg + i] * 8 + h;
                g_s[o] = __expf(g_s[o] - mh) * inv;
            }
        }
        __syncwarp();
        // pass 3: U[d][b][dim] = sum over live edges of a_b * (h[src] * F(r))
        for (int i = 0; i < lcnt; i++) {
            int lp = lbeg + i;
            int e = g_lpos[lp];
            int s = g_lsrc[lp];
            float rr = g_lr[lp];
            float t = rr * ((float)NTAB / 8.f);
            int i0 = (int)t;
            float fr = t - (float)i0;
            float4 a0 = *(const float4*)(g_s + (size_t)e * 8);
            float4 a1 = *(const float4*)(g_s + (size_t)e * 8 + 4);
            float4 hv = *(const float4*)(g_h + (size_t)s * 128 + lane * 4);
            const float* tp = g_tab + (size_t)i0 * 128 + lane * 4;
            float4 w0 = *(const float4*)tp;
            float4 w1 = *(const float4*)(tp + 128);
            float wx = w0.x + fr * (w1.x - w0.x);
            float wy = w0.y + fr * (w1.y - w0.y);
            float wz = w0.z + fr * (w1.z - w0.z);
            float ww = w0.w + fr * (w1.w - w0.w);
            float u0 = hv.x * wx, u1 = hv.y * wy;
            float u2 = hv.z * wz, u3 = hv.w * ww;
            float ab[8] = {a0.x, a0.y, a0.z, a0.w, a1.x, a1.y, a1.z, a1.w};
#pragma unroll
            for (int b = 0; b < 8; b++) {
                acc[b][0] += ab[b] * u0; acc[b][1] += ab[b] * u1;
                acc[b][2] += ab[b] * u2; acc[b][3] += ab[b] * u3;
            }
        }
    }
    __half* up = g_U + (size_t)d * 1024 + lane * 4;
#pragma unroll
    for (int b = 0; b < 8; b++) {
        __half2 p0 = __floats2half2_rn(acc[b][0], acc[b][1]);
        __half2 p1 = __floats2half2_rn(acc[b][2], acc[b][3]);
        uint2 packed = make_uint2(*(uint32_t*)&p0, *(uint32_t*)&p1);
        *(uint2*)(up + b * 128) = packed;
    }
}

// ---------------- ugemm: msg[:, 16b:16b+16] = U[:, b, :] @ Wv[:, 16b:16b+16] ----------------
__global__ __launch_bounds__(256) void k_ugemm(const float* __restrict__ Wv) {
    extern __shared__ float sm[];
    float* sU = sm;            // 128 atoms x 128 dims (64 KB)
    float* sW = sm + 16384;    // 128 x 16 (8 KB)
    int b = blockIdx.y, n0 = blockIdx.x * 128, tid = threadIdx.x;

    for (int i = tid; i < 128 * 16; i += 256) {
        int k = i >> 4, c = i & 15;
        sW[i] = Wv[k * 128 + b * 16 + c];
    }
    for (int i = tid; i < 128 * 32; i += 256) {
        int r = i >> 5, kq = i & 31;
        int n = n0 + r;
        float4 v = make_float4(0.f, 0.f, 0.f, 0.f);
        if (n < NA) {
            uint2 raw = *(const uint2*)(g_U + (size_t)n * 1024 + b * 128 + kq * 4);
            __half2 p0 = *(__half2*)&raw.x;
            __half2 p1 = *(__half2*)&raw.y;
            float2 f0 = __half22float2(p0), f1 = __half22float2(p1);
            v = make_float4(f0.x, f0.y, f1.x, f1.y);
        }
        *(float4*)(sU + r * 128 + kq * 4) = v;
    }
    __syncthreads();

    int col = tid & 15, rg = tid >> 4;   // rows rg*8..rg*8+7
    float acc[8] = {0.f, 0.f, 0.f, 0.f, 0.f, 0.f, 0.f, 0.f};
#pragma unroll 4
    for (int k4 = 0; k4 < 128; k4 += 4) {
        float bw[4];
#pragma unroll
        for (int q = 0; q < 4; q++) bw[q] = sW[(k4 + q) * 16 + col];
#pragma unroll
        for (int j = 0; j < 8; j++) {
            float4 av = *(const float4*)(sU + (rg * 8 + j) * 128 + k4);
            acc[j] += av.x * bw[0] + av.y * bw[1] + av.z * bw[2] + av.w * bw[3];
        }
    }
#pragma unroll
    for (int j = 0; j < 8; j++) {
        int n = n0 + rg * 8 + j;
        if (n < NA) g_msg[(size_t)n * 128 + b * 16 + col] = acc[j];
    }
}

// ---------------- final: x += msg @ Wo; reset counters for next call ----------------
__global__ __launch_bounds__(512) void k_out(float* __restrict__ x,
                                             const float* __restrict__ Wo) {
    extern __shared__ float sm[];
    float* sA  = sm;
    float* sBt = sA + 16384;
    int tid = threadIdx.x, lane = tid & 31, w = tid >> 5;
    int wm = w & 3, wn = w >> 2;
    int g = lane >> 2, t4 = lane & 3;
    int n0 = blockIdx.x * 128;

    int gidx = blockIdx.x * 512 + tid;
    if (gidx < NA) { g_cnt_all[gidx] = 0; g_cnt_live[gidx] = 0; }

    for (int i = tid; i < 128 * 128; i += 512) {
        int r = i >> 7, c = i & 127;
        int n = n0 + r;
        sA[fragA_idx<16>(r, c)] = (n < NA) ? f2tff(g_msg[(size_t)n * 128 + c]) : 0.f;
    }
    for (int i = tid; i < 128 * 128; i += 512) {
        int k = i >> 7, n = i & 127;
        sBt[fragB_idx<16>(k, n)] = f2tff(Wo[i]);
    }
    __syncthreads();

    float4 acc[2][4];
    zacc4(acc);
    mma_tile_frag<16>(sA, sBt, wm, wn, lane, acc);
#pragma unroll
    for (int mi = 0; mi < 2; mi++) {
        int r = 32 * wm + 16 * mi + g;
#pragma unroll
        for (int jl = 0; jl < 4; jl++) {
            int c = 32 * wn + 8 * jl + 2 * t4;
            float4 d = acc[mi][jl];
            int n1 = n0 + r, n2 = n1 + 8;
            if (n1 < NA) {
                float2 o = *(float2*)(x + (size_t)n1 * 128 + c);
                o.x += d.x; o.y += d.y;
                *(float2*)(x + (size_t)n1 * 128 + c) = o;
            }
            if (n2 < NA) {
                float2 o = *(float2*)(x + (size_t)n2 * 128 + c);
                o.x += d.z; o.y += d.w;
                *(float2*)(x + (size_t)n2 * 128 + c) = o;
            }
        }
    }
}

// ---------------- launch ----------------
extern "C" void kernel_launch(void* const* d_in, const int* in_sizes, int n_in,
                              void* d_out, int out_size) {
    const float* xyz = (const float*)d_in[0];
    const float* emb = (const float*)d_in[1];
    const float* te  = (const float*)d_in[2];
    const float* Wl  = (const float*)d_in[3];
    const float* bl  = (const float*)d_in[4];
    const float* W1f = (const float*)d_in[5];
    const float* b1f = (const float*)d_in[6];
    const float* W2f = (const float*)d_in[7];
    const float* b2f = (const float*)d_in[8];
    const float* Wq  = (const float*)d_in[9];
    const float* Wk  = (const float*)d_in[10];
    const float* Wv  = (const float*)d_in[11];
    const float* Wo  = (const float*)d_in[12];
    const int*   z   = (const int*)d_in[13];
    const int*   src = (const int*)d_in[14];
    const int*   dst = (const int*)d_in[15];
    float* x = (float*)d_out;

    const int SM_TAB   = (4096 + 16384 + 4096 + 4096 + 16384 + 3 * 128) * 4;
    const int SM_OQK   = (2 * 16384) * 4;
    const int SM_UGEMM = (16384 + 128 * 16) * 4;   // 73728
    const int SM_OUT   = (2 * 16384) * 4;

    cudaFuncSetAttribute(k_tab,   cudaFuncAttributeMaxDynamicSharedMemorySize, SM_TAB);
    cudaFuncSetAttribute(k_oqk,   cudaFuncAttributeMaxDynamicSharedMemorySize, SM_OQK);
    cudaFuncSetAttribute(k_ugemm, cudaFuncAttributeMaxDynamicSharedMemorySize, SM_UGEMM);
    cudaFuncSetAttribute(k_out,   cudaFuncAttributeMaxDynamicSharedMemorySize, SM_OUT);

    k_hist<<<NE / 256, 256>>>(xyz, src, dst);
    k_scan<<<1, 512>>>();
    k_scatter<<<NE / 256, 256>>>(xyz, src, dst);
    k_tab<<<(NTAB + 1 + 127) / 128, 512, SM_TAB>>>(Wl, bl, W1f, b1f, W2f, b2f);
    k_embed<<<(NA * DD + 255) / 256, 256>>>(emb, z, x);

    const int NBLK = (NA + 127) / 128;   // 157
    dim3 ug(NBLK, 8);
    for (int it = 0; it < NIT; it++) {
        k_oqk<<<NBLK, 512, SM_OQK>>>(x, te, Wo, Wq, Wk, it);
        k_attn<<<(NA * 32 + 255) / 256, 256>>>();
        k_ugemm<<<ug, 256, SM_UGEMM>>>(Wv);
    }
    k_out<<<NBLK, 512, SM_OUT>>>(x, Wo);
}

// round 15
// speedup vs baseline: 1.4696x; 1.0096x over previous
#include <cuda_runtime.h>
#include <cuda_fp16.h>
#include <math.h>
#include <stdint.h>

#define NA 20000
#define NE 640000
#define DD 128
#define GG 32
#define HH 8
#define NIT 4
#define NSM 148
#define NTAB 4096

// ---------------- device scratch ----------------
__device__ __half   g_tab[(NTAB + 1) * DD];   // Wfil lookup table over r in [0,8], fp16
__device__ int      g_ssrc[NE];     // src, sorted by dst
__device__ int      g_lsrc[NE];     // live subset, sorted by dst
__device__ int      g_lpos[NE];
__device__ float    g_lr[NE];       // live edge distance
__device__ int      g_cnt_all[NA];  // statically zero; re-zeroed by final k_out
__device__ int      g_cnt_live[NA];
__device__ int      g_off_all[NA];
__device__ int      g_off_live[NA];
__device__ int      g_nlive;
__device__ __half   g_h[NA * DD];   // fp16
__device__ float    g_Q[NA * DD];   // fp32 (read once per warp)
__device__ __half   g_K[NA * DD];   // fp16 (gathered per edge)
__device__ float    g_s[NE * HH];
__device__ __half   g_U[(size_t)NA * 1024];   // per-atom [8 heads][128 dims], fp16
__device__ float    g_msg[NA * DD];

__device__ __forceinline__ float edge_r(const float* xyz, int s, int d) {
    float dx = xyz[3 * s]     - xyz[3 * d];
    float dy = xyz[3 * s + 1] - xyz[3 * d + 1];
    float dz = xyz[3 * s + 2] - xyz[3 * d + 2];
    return sqrtf(dx * dx + dy * dy + dz * dz + 1e-12f);
}
__device__ __forceinline__ float4 h4tof4(uint2 raw) {
    __half2 p0 = *(__half2*)&raw.x;
    __half2 p1 = *(__half2*)&raw.y;
    float2 f0 = __half22float2(p0), f1 = __half22float2(p1);
    return make_float4(f0.x, f0.y, f1.x, f1.y);
}
__device__ __forceinline__ uint2 f4toh4(float a, float b, float c, float d) {
    __half2 p0 = __floats2half2_rn(a, b);
    __half2 p1 = __floats2half2_rn(c, d);
    return make_uint2(*(uint32_t*)&p0, *(uint32_t*)&p1);
}

// ---------------- tf32 MMA core with fragment-major smem ----------------
__device__ __forceinline__ uint32_t f2tf(float f) {
    uint32_t u;
    asm("cvt.rna.tf32.f32 %0, %1;" : "=r"(u) : "f"(f));
    return u;
}
__device__ __forceinline__ float f2tff(float f) { return __uint_as_float(f2tf(f)); }

__device__ __forceinline__ void mma8(float4& d,
                                     uint32_t a0, uint32_t a1, uint32_t a2, uint32_t a3,
                                     uint32_t b0, uint32_t b1) {
    asm volatile(
        "mma.sync.aligned.m16n8k8.row.col.f32.tf32.tf32.f32 "
        "{%0,%1,%2,%3},{%4,%5,%6,%7},{%8,%9},{%0,%1,%2,%3};"
        : "+f"(d.x), "+f"(d.y), "+f"(d.z), "+f"(d.w)
        : "r"(a0), "r"(a1), "r"(a2), "r"(a3), "r"(b0), "r"(b1));
}
template <int KB>
__device__ __forceinline__ int fragA_idx(int r, int k) {
    return (((r >> 4) * KB + (k >> 3)) << 7) + (((r & 7) * 4 + (k & 3)) << 2)
         + ((r >> 3) & 1) + (((k >> 2) & 1) << 1);
}
template <int KB>
__device__ __forceinline__ int fragB_idx(int k, int n) {
    return (((n >> 4) * KB + (k >> 3)) << 7) + (((n & 7) * 4 + (k & 3)) << 2)
         + (((n >> 3) & 1) << 1) + ((k >> 2) & 1);
}
#define FAU(x) __float_as_uint(x)
template <int KB>
__device__ __forceinline__ void mma_tile_frag(const float* __restrict__ sA,
                                              const float* __restrict__ sB,
                                              int wm, int wn, int lane,
                                              float4 acc[2][4]) {
    const float4* A = (const float4*)sA;
    const float4* B = (const float4*)sB;
#pragma unroll
    for (int kk = 0; kk < KB; kk++) {
        float4 a0 = A[((2 * wm)     * KB + kk) * 32 + lane];
        float4 a1 = A[((2 * wm + 1) * KB + kk) * 32 + lane];
        float4 b0 = B[((2 * wn)     * KB + kk) * 32 + lane];
        float4 b1 = B[((2 * wn + 1) * KB + kk) * 32 + lane];
        mma8(acc[0][0], FAU(a0.x), FAU(a0.y), FAU(a0.z), FAU(a0.w), FAU(b0.x), FAU(b0.y));
        mma8(acc[1][0], FAU(a1.x), FAU(a1.y), FAU(a1.z), FAU(a1.w), FAU(b0.x), FAU(b0.y));
        mma8(acc[0][1], FAU(a0.x), FAU(a0.y), FAU(a0.z), FAU(a0.w), FAU(b0.z), FAU(b0.w));
        mma8(acc[1][1], FAU(a1.x), FAU(a1.y), FAU(a1.z), FAU(a1.w), FAU(b0.z), FAU(b0.w));
        mma8(acc[0][2], FAU(a0.x), FAU(a0.y), FAU(a0.z), FAU(a0.w), FAU(b1.x), FAU(b1.y));
        mma8(acc[1][2], FAU(a1.x), FAU(a1.y), FAU(a1.z), FAU(a1.w), FAU(b1.x), FAU(b1.y));
        mma8(acc[0][3], FAU(a0.x), FAU(a0.y), FAU(a0.z), FAU(a0.w), FAU(b1.z), FAU(b1.w));
        mma8(acc[1][3], FAU(a1.x), FAU(a1.y), FAU(a1.z), FAU(a1.w), FAU(b1.z), FAU(b1.w));
    }
}
__device__ __forceinline__ void zacc4(float4 acc[2][4]) {
#pragma unroll
    for (int i = 0; i < 2; i++)
#pragma unroll
        for (int j = 0; j < 4; j++) acc[i][j] = make_float4(0.f, 0.f, 0.f, 0.f);
}

// ---------------- setup ----------------
__global__ void k_hist(const float* __restrict__ xyz, const int* __restrict__ src,
                       const int* __restrict__ dst) {
    int e = blockIdx.x * blockDim.x + threadIdx.x;
    if (e >= NE) return;
    int s = src[e], d = dst[e];
    atomicAdd(&g_cnt_all[d], 1);
    if (edge_r(xyz, s, d) < 8.f) atomicAdd(&g_cnt_live[d], 1);
}

__global__ __launch_bounds__(512) void k_scan() {
    __shared__ int part[512];
    __shared__ int total;
    int t = threadIdx.x;
    const int CH = (NA + 511) / 512;
#pragma unroll 1
    for (int pass = 0; pass < 2; pass++) {
        int* cnt = pass ? g_cnt_live : g_cnt_all;
        int* off = pass ? g_off_live : g_off_all;
        int lo = t * CH, hi = min(lo + CH, NA);
        int s = 0;
        for (int i = lo; i < hi; i++) s += cnt[i];
        part[t] = s;
        __syncthreads();
        if (t == 0) {
            int run = 0;
            for (int i = 0; i < 512; i++) { int v = part[i]; part[i] = run; run += v; }
            total = run;
        }
        __syncthreads();
        int run = part[t];
        for (int i = lo; i < hi; i++) { int v = cnt[i]; off[i] = run; run += v; cnt[i] = 0; }
        if (pass == 1 && t == 0) g_nlive = total;
        __syncthreads();
    }
}

__global__ void k_scatter(const float* __restrict__ xyz, const int* __restrict__ src,
                          const int* __restrict__ dst) {
    int e = blockIdx.x * blockDim.x + threadIdx.x;
    if (e >= NE) return;
    int s = src[e], d = dst[e];
    int pos = g_off_all[d] + atomicAdd(&g_cnt_all[d], 1);
    g_ssrc[pos] = s;
    float r = edge_r(xyz, s, d);
    if (r < 8.f) {
        int lp = g_off_live[d] + atomicAdd(&g_cnt_live[d], 1);
        g_lsrc[lp] = s; g_lpos[lp] = pos; g_lr[lp] = r;
    }
}

__global__ void k_embed(const float* __restrict__ emb, const int* __restrict__ z,
                        float* __restrict__ x) {
    int i = blockIdx.x * blockDim.x + threadIdx.x;
    if (i < NA * DD) {
        int n = i >> 7, d = i & 127;
        x[i] = emb[z[n] * DD + d];
    }
}

// ---------------- Wfil table build (fp16 output) ----------------
__global__ __launch_bounds__(512) void k_tab(
    const float* __restrict__ Wl, const float* __restrict__ bl,
    const float* __restrict__ W1f, const float* __restrict__ b1f,
    const float* __restrict__ W2f, const float* __restrict__ b2f) {
    extern __shared__ float sm[];
    float* sf   = sm;
    float* sg   = sf + 4096;
    float* sW1t = sg + 16384;
    float* sWlt = sW1t + 4096;
    float* sW2t = sWlt + 4096;
    float* sC   = sW2t + 16384;       // 128
    float* sb1  = sC + 128;
    float* sb   = sb1 + 128;

    int tid = threadIdx.x, lane = tid & 31, w = tid >> 5;
    int wm = w & 3, wn = w >> 2;
    int g = lane >> 2, t4 = lane & 3;

    for (int i = tid; i < 32 * 128; i += 512) {
        int k = i >> 7, n = i & 127;
        sW1t[fragB_idx<4>(k, n)] = f2tff(W1f[i]);
        sWlt[fragB_idx<4>(k, n)] = f2tff(Wl[i]);
    }
    for (int i = tid; i < 128 * 128; i += 512) {
        int k = i >> 7, n = i & 127;
        sW2t[fragB_idx<16>(k, n)] = f2tff(W2f[i]);
    }
    if (tid < 128) { sb1[tid] = b1f[tid]; sb[tid] = bl[tid] + b2f[tid]; }

    const int NROWS = NTAB + 1;
    for (int tt = blockIdx.x; tt * 128 < NROWS; tt += gridDim.x) {
        if (tid < 128) {
            int li = tt * 128 + tid;
            float r = (float)li * (8.f / NTAB);
            sC[tid] = (r < 8.f) ? (0.5f * (cospif(r * 0.125f) + 1.f)) : 0.f;
        }
        __syncthreads();
        {
            int el = tid >> 2, kb = (tid & 3) * 8;
            float r = (float)(tt * 128 + el) * (8.f / NTAB);
#pragma unroll
            for (int q = 0; q < 8; q++) {
                int k = kb + q;
                float off = (float)k * (8.f / 31.f);
                float u = (r - off) * (31.f / 8.f);
                sf[fragA_idx<4>(el, k)] = f2tff(__expf(-0.5f * u * u));
            }
        }
        __syncthreads();

        float4 acc[2][4];
        zacc4(acc);
        mma_tile_frag<4>(sf, sW1t, wm, wn, lane, acc);
        __syncthreads();
#pragma unroll
        for (int mi = 0; mi < 2; mi++) {
            int r = 32 * wm + 16 * mi + g;
#pragma unroll
            for (int jl = 0; jl < 4; jl++) {
                int c = 32 * wn + 8 * jl + 2 * t4;
                float4 d = acc[mi][jl];
                float v0 = d.x + sb1[c], v1 = d.y + sb1[c + 1];
                float v2 = d.z + sb1[c], v3 = d.w + sb1[c + 1];
                sg[fragA_idx<16>(r, c)]         = f2tff(v0 / (1.f + __expf(-v0)));
                sg[fragA_idx<16>(r, c + 1)]     = f2tff(v1 / (1.f + __expf(-v1)));
                sg[fragA_idx<16>(r + 8, c)]     = f2tff(v2 / (1.f + __expf(-v2)));
                sg[fragA_idx<16>(r + 8, c + 1)] = f2tff(v3 / (1.f + __expf(-v3)));
            }
        }
        __syncthreads();

        zacc4(acc);
        mma_tile_frag<4>(sf, sWlt, wm, wn, lane, acc);
        mma_tile_frag<16>(sg, sW2t, wm, wn, lane, acc);

#pragma unroll
        for (int mi = 0; mi < 2; mi++) {
            int r = 32 * wm + 16 * mi + g;
#pragma unroll
            for (int jl = 0; jl < 4; jl++) {
                int c = 32 * wn + 8 * jl + 2 * t4;
                float4 d = acc[mi][jl];
                int li0 = tt * 128 + r, li1 = li0 + 8;
                if (li0 < NROWS) {
                    float Cv = sC[r];
                    __half2 p = __floats2half2_rn((d.x + sb[c]) * Cv, (d.y + sb[c + 1]) * Cv);
                    *(__half2*)(g_tab + (size_t)li0 * 128 + c) = p;
                }
                if (li1 < NROWS) {
                    float Cv = sC[r + 8];
                    __half2 p = __floats2half2_rn((d.z + sb[c]) * Cv, (d.w + sb[c + 1]) * Cv);
                    *(__half2*)(g_tab + (size_t)li1 * 128 + c) = p;
                }
            }
        }
        __syncthreads();
    }
}

// ---------------- fused out+hqk: x += msg@Wo; h = x+te; Q = h@Wq; K = h@Wk ----------------
__global__ __launch_bounds__(512) void k_oqk(float* __restrict__ x,
                                             const float* __restrict__ te,
                                             const float* __restrict__ Wo,
                                             const float* __restrict__ Wq,
                                             const float* __restrict__ Wk, int it) {
    extern __shared__ float sm[];
    float* sA = sm;
    float* sB = sm + 16384;
    int tid = threadIdx.x, lane = tid & 31, w = tid >> 5;
    int wm = w & 3, wn = w >> 2;
    int g = lane >> 2, t4 = lane & 3;
    int n0 = blockIdx.x * 128;

    float4 acc[2][4];
    zacc4(acc);
    if (it > 0) {
        for (int i = tid; i < 128 * 128; i += 512) {
            int r = i >> 7, c = i & 127, n = n0 + r;
            sA[fragA_idx<16>(r, c)] = (n < NA) ? f2tff(g_msg[(size_t)n * 128 + c]) : 0.f;
        }
        for (int i = tid; i < 128 * 128; i += 512) {
            int k = i >> 7, n = i & 127;
            sB[fragB_idx<16>(k, n)] = f2tff(Wo[i]);
        }
        __syncthreads();
        mma_tile_frag<16>(sA, sB, wm, wn, lane, acc);
        __syncthreads();
    }
#pragma unroll
    for (int mi = 0; mi < 2; mi++) {
        int r = 32 * wm + 16 * mi + g;
#pragma unroll
        for (int jl = 0; jl < 4; jl++) {
            int c = 32 * wn + 8 * jl + 2 * t4;
            float4 d = acc[mi][jl];
            float te0 = te[it * 128 + c], te1 = te[it * 128 + c + 1];
            int n1 = n0 + r, n2 = n1 + 8;
            float h00 = 0.f, h01 = 0.f, h10 = 0.f, h11 = 0.f;
            if (n1 < NA) {
                float2 xv = *(float2*)(x + (size_t)n1 * 128 + c);
                xv.x += d.x; xv.y += d.y;
                *(float2*)(x + (size_t)n1 * 128 + c) = xv;
                h00 = xv.x + te0; h01 = xv.y + te1;
                *(__half2*)(g_h + (size_t)n1 * 128 + c) = __floats2half2_rn(h00, h01);
            }
            if (n2 < NA) {
                float2 xv = *(float2*)(x + (size_t)n2 * 128 + c);
                xv.x += d.z; xv.y += d.w;
                *(float2*)(x + (size_t)n2 * 128 + c) = xv;
                h10 = xv.x + te0; h11 = xv.y + te1;
                *(__half2*)(g_h + (size_t)n2 * 128 + c) = __floats2half2_rn(h10, h11);
            }
            sA[fragA_idx<16>(r, c)]         = f2tff(h00);
            sA[fragA_idx<16>(r, c + 1)]     = f2tff(h01);
            sA[fragA_idx<16>(r + 8, c)]     = f2tff(h10);
            sA[fragA_idx<16>(r + 8, c + 1)] = f2tff(h11);
        }
    }
    for (int i = tid; i < 128 * 128; i += 512) {
        int k = i >> 7, n = i & 127;
        sB[fragB_idx<16>(k, n)] = f2tff(Wq[i]);
    }
    __syncthreads();
    zacc4(acc);
    mma_tile_frag<16>(sA, sB, wm, wn, lane, acc);
#pragma unroll
    for (int mi = 0; mi < 2; mi++) {
        int r = 32 * wm + 16 * mi + g;
#pragma unroll
        for (int jl = 0; jl < 4; jl++) {
            int c = 32 * wn + 8 * jl + 2 * t4;
            float4 d = acc[mi][jl];
            int n1 = n0 + r, n2 = n1 + 8;
            if (n1 < NA) *(float2*)(g_Q + (size_t)n1 * 128 + c) = make_float2(d.x, d.y);
            if (n2 < NA) *(float2*)(g_Q + (size_t)n2 * 128 + c) = make_float2(d.z, d.w);
        }
    }
    __syncthreads();
    for (int i = tid; i < 128 * 128; i += 512) {
        int k = i >> 7, n = i & 127;
        sB[fragB_idx<16>(k, n)] = f2tff(Wk[i]);
    }
    __syncthreads();
    zacc4(acc);
    mma_tile_frag<16>(sA, sB, wm, wn, lane, acc);
#pragma unroll
    for (int mi = 0; mi < 2; mi++) {
        int r = 32 * wm + 16 * mi + g;
#pragma unroll
        for (int jl = 0; jl < 4; jl++) {
            int c = 32 * wn + 8 * jl + 2 * t4;
            float4 d = acc[mi][jl];
            int n1 = n0 + r, n2 = n1 + 8;
            if (n1 < NA) *(__half2*)(g_K + (size_t)n1 * 128 + c) = __floats2half2_rn(d.x, d.y);
            if (n2 < NA) *(__half2*)(g_K + (size_t)n2 * 128 + c) = __floats2half2_rn(d.z, d.w);
        }
    }
}

// ---------------- fused attention: softmax + per-atom U aggregation ----------------
__global__ __launch_bounds__(256) void k_attn() {
    int warp = (blockIdx.x * blockDim.x + threadIdx.x) >> 5;
    int lane = threadIdx.x & 31;
    if (warp >= NA) return;
    int d = warp;
    int beg = g_off_all[d], cnt = g_cnt_all[d];

    float acc[8][4];
#pragma unroll
    for (int b = 0; b < 8; b++)
#pragma unroll
        for (int j = 0; j < 4; j++) acc[b][j] = 0.f;

    int lbeg = g_off_live[d], lcnt = g_cnt_live[d];
    if (cnt > 0) {
        // pass 1: scores + online per-head max/denominator (ALL edges)
        float4 q = *(const float4*)(g_Q + (size_t)d * 128 + lane * 4);
        float m = -1e30f, den = 0.f;
        for (int i = 0; i < cnt; i++) {
            int e = beg + i;
            int s = g_ssrc[e];
            float4 kv = h4tof4(*(const uint2*)(g_K + (size_t)s * 128 + lane * 4));
            float p = q.x * kv.x + q.y * kv.y + q.z * kv.z + q.w * kv.w;
            p += __shfl_xor_sync(0xffffffffu, p, 1);
            p += __shfl_xor_sync(0xffffffffu, p, 2);
            p *= 0.25f;
            float mn = fmaxf(m, p);
            den = den * __expf(m - mn) + __expf(p - mn);
            m = mn;
            float t = __shfl_sync(0xffffffffu, p, (lane & 7) * 4);
            if (lane < 8) g_s[(size_t)e * 8 + lane] = t;
        }
        __syncwarp();
        // pass 2: normalize a into g_s for LIVE edges only
        float mh  = __shfl_sync(0xffffffffu, m,   (lane & 7) * 4);
        float dh  = __shfl_sync(0xffffffffu, den, (lane & 7) * 4);
        float inv = 1.f / (dh + 1e-12f);
        int h = lane & 7, eo = lane >> 3;
        for (int base = 0; base < lcnt; base += 4) {
            int i = base + eo;
            if (i < lcnt) {
                size_t o = (size_t)g_lpos[lbeg + i] * 8 + h;
                g_s[o] = __expf(g_s[o] - mh) * inv;
            }
        }
        __syncwarp();
        // pass 3: U[d][b][dim] = sum over live edges of a_b * (h[src] * F(r))
        for (int i = 0; i < lcnt; i++) {
            int lp = lbeg + i;
            int e = g_lpos[lp];
            int s = g_lsrc[lp];
            float rr = g_lr[lp];
            float t = rr * ((float)NTAB / 8.f);
            int i0 = (int)t;
            float fr = t - (float)i0;
            float4 a0 = *(const float4*)(g_s + (size_t)e * 8);
            float4 a1 = *(const float4*)(g_s + (size_t)e * 8 + 4);
            float4 hv = h4tof4(*(const uint2*)(g_h + (size_t)s * 128 + lane * 4));
            const __half* tp = g_tab + (size_t)i0 * 128 + lane * 4;
            float4 w0 = h4tof4(*(const uint2*)tp);
            float4 w1 = h4tof4(*(const uint2*)(tp + 128));
            float wx = w0.x + fr * (w1.x - w0.x);
            float wy = w0.y + fr * (w1.y - w0.y);
            float wz = w0.z + fr * (w1.z - w0.z);
            float ww = w0.w + fr * (w1.w - w0.w);
            float u0 = hv.x * wx, u1 = hv.y * wy;
            float u2 = hv.z * wz, u3 = hv.w * ww;
            float ab[8] = {a0.x, a0.y, a0.z, a0.w, a1.x, a1.y, a1.z, a1.w};
#pragma unroll
            for (int b = 0; b < 8; b++) {
                acc[b][0] += ab[b] * u0; acc[b][1] += ab[b] * u1;
                acc[b][2] += ab[b] * u2; acc[b][3] += ab[b] * u3;
            }
        }
    }
    __half* up = g_U + (size_t)d * 1024 + lane * 4;
#pragma unroll
    for (int b = 0; b < 8; b++)
        *(uint2*)(up + b * 128) = f4toh4(acc[b][0], acc[b][1], acc[b][2], acc[b][3]);
}

// ---------------- ugemm: msg[:, 16b:16b+16] = U[:, b, :] @ Wv[:, 16b:16b+16] ----------------
__global__ __launch_bounds__(256) void k_ugemm(const float* __restrict__ Wv) {
    extern __shared__ float sm[];
    float* sU = sm;            // 128 atoms x 128 dims (64 KB)
    float* sW = sm + 16384;    // 128 x 16 (8 KB)
    int b = blockIdx.y, n0 = blockIdx.x * 128, tid = threadIdx.x;

    for (int i = tid; i < 128 * 16; i += 256) {
        int k = i >> 4, c = i & 15;
        sW[i] = Wv[k * 128 + b * 16 + c];
    }
    for (int i = tid; i < 128 * 32; i += 256) {
        int r = i >> 5, kq = i & 31;
        int n = n0 + r;
        float4 v = make_float4(0.f, 0.f, 0.f, 0.f);
        if (n < NA)
            v = h4tof4(*(const uint2*)(g_U + (size_t)n * 1024 + b * 128 + kq * 4));
        *(float4*)(sU + r * 128 + kq * 4) = v;
    }
    __syncthreads();

    int col = tid & 15, rg = tid >> 4;   // rows rg*8..rg*8+7
    float acc[8] = {0.f, 0.f, 0.f, 0.f, 0.f, 0.f, 0.f, 0.f};
#pragma unroll 4
    for (int k4 = 0; k4 < 128; k4 += 4) {
        float bw[4];
#pragma unroll
        for (int q = 0; q < 4; q++) bw[q] = sW[(k4 + q) * 16 + col];
#pragma unroll
        for (int j = 0; j < 8; j++) {
            float4 av = *(const float4*)(sU + (rg * 8 + j) * 128 + k4);
            acc[j] += av.x * bw[0] + av.y * bw[1] + av.z * bw[2] + av.w * bw[3];
        }
    }
#pragma unroll
    for (int j = 0; j < 8; j++) {
        int n = n0 + rg * 8 + j;
        if (n < NA) g_msg[(size_t)n * 128 + b * 16 + col] = acc[j];
    }
}

// ---------------- final: x += msg @ Wo; reset counters for next call ----------------
__global__ __launch_bounds__(512) void k_out(float* __restrict__ x,
                                             const float* __restrict__ Wo) {
    extern __shared__ float sm[];
    float* sA  = sm;
    float* sBt = sA + 16384;
    int tid = threadIdx.x, lane = tid & 31, w = tid >> 5;
    int wm = w & 3, wn = w >> 2;
    int g = lane >> 2, t4 = lane & 3;
    int n0 = blockIdx.x * 128;

    int gidx = blockIdx.x * 512 + tid;
    if (gidx < NA) { g_cnt_all[gidx] = 0; g_cnt_live[gidx] = 0; }

    for (int i = tid; i < 128 * 128; i += 512) {
        int r = i >> 7, c = i & 127;
        int n = n0 + r;
        sA[fragA_idx<16>(r, c)] = (n < NA) ? f2tff(g_msg[(size_t)n * 128 + c]) : 0.f;
    }
    for (int i = tid; i < 128 * 128; i += 512) {
        int k = i >> 7, n = i & 127;
        sBt[fragB_idx<16>(k, n)] = f2tff(Wo[i]);
    }
    __syncthreads();

    float4 acc[2][4];
    zacc4(acc);
    mma_tile_frag<16>(sA, sBt, wm, wn, lane, acc);
#pragma unroll
    for (int mi = 0; mi < 2; mi++) {
        int r = 32 * wm + 16 * mi + g;
#pragma unroll
        for (int jl = 0; jl < 4; jl++) {
            int c = 32 * wn + 8 * jl + 2 * t4;
            float4 d = acc[mi][jl];
            int n1 = n0 + r, n2 = n1 + 8;
            if (n1 < NA) {
                float2 o = *(float2*)(x + (size_t)n1 * 128 + c);
                o.x += d.x; o.y += d.y;
                *(float2*)(x + (size_t)n1 * 128 + c) = o;
            }
            if (n2 < NA) {
                float2 o = *(float2*)(x + (size_t)n2 * 128 + c);
                o.x += d.z; o.y += d.w;
                *(float2*)(x + (size_t)n2 * 128 + c) = o;
            }
        }
    }
}

// ---------------- launch ----------------
extern "C" void kernel_launch(void* const* d_in, const int* in_sizes, int n_in,
                              void* d_out, int out_size) {
    const float* xyz = (const float*)d_in[0];
    const float* emb = (const float*)d_in[1];
    const float* te  = (const float*)d_in[2];
    const float* Wl  = (const float*)d_in[3];
    const float* bl  = (const float*)d_in[4];
    const float* W1f = (const float*)d_in[5];
    const float* b1f = (const float*)d_in[6];
    const float* W2f = (const float*)d_in[7];
    const float* b2f = (const float*)d_in[8];
    const float* Wq  = (const float*)d_in[9];
    const float* Wk  = (const float*)d_in[10];
    const float* Wv  = (const float*)d_in[11];
    const float* Wo  = (const float*)d_in[12];
    const int*   z   = (const int*)d_in[13];
    const int*   src = (const int*)d_in[14];
    const int*   dst = (const int*)d_in[15];
    float* x = (float*)d_out;

    const int SM_TAB   = (4096 + 16384 + 4096 + 4096 + 16384 + 3 * 128) * 4;
    const int SM_OQK   = (2 * 16384) * 4;
    const int SM_UGEMM = (16384 + 128 * 16) * 4;   // 73728
    const int SM_OUT   = (2 * 16384) * 4;

    cudaFuncSetAttribute(k_tab,   cudaFuncAttributeMaxDynamicSharedMemorySize, SM_TAB);
    cudaFuncSetAttribute(k_oqk,   cudaFuncAttributeMaxDynamicSharedMemorySize, SM_OQK);
    cudaFuncSetAttribute(k_ugemm, cudaFuncAttributeMaxDynamicSharedMemorySize, SM_UGEMM);
    cudaFuncSetAttribute(k_out,   cudaFuncAttributeMaxDynamicSharedMemorySize, SM_OUT);

    k_hist<<<NE / 256, 256>>>(xyz, src, dst);
    k_scan<<<1, 512>>>();
    k_scatter<<<NE / 256, 256>>>(xyz, src, dst);
    k_tab<<<(NTAB + 1 + 127) / 128, 512, SM_TAB>>>(Wl, bl, W1f, b1f, W2f, b2f);
    k_embed<<<(NA * DD + 255) / 256, 256>>>(emb, z, x);

    const int NBLK = (NA + 127) / 128;   // 157
    dim3 ug(NBLK, 8);
    for (int it = 0; it < NIT; it++) {
        k_oqk<<<NBLK, 512, SM_OQK>>>(x, te, Wo, Wq, Wk, it);
        k_attn<<<(NA * 32 + 255) / 256, 256>>>();
        k_ugemm<<<ug, 256, SM_UGEMM>>>(Wv);
    }
    k_out<<<NBLK, 512, SM_OUT>>>(x, Wo);
}